// round 2
// baseline (speedup 1.0000x reference)
#include <cuda_runtime.h>
#include <math.h>

// Problem constants
#define BB  4
#define TQ  1024
#define TKV 2048
#define DD  1024
#define HH  16
#define DHD 64

// GEMM tiling
#define BM 64
#define BN 64
#define BK 16

// Scratch (device globals; no allocations allowed)
__device__ float g_q[BB * TQ * DD];    // scaled q (scale^2 folded in)
__device__ float g_wv[BB * TQ * DD];   // attention output before Wo

// ---------------------------------------------------------------------------
// Copy the old (first TQ rows per batch) part of k/v cache into the output.
// dst linear index == src linear index for that region.
// ---------------------------------------------------------------------------
__global__ void copy_old_cache(const float4* __restrict__ ksrc,
                               const float4* __restrict__ vsrc,
                               float4* __restrict__ kdst,
                               float4* __restrict__ vdst) {
    int i = blockIdx.x * blockDim.x + threadIdx.x;   // over BB*TQ*DD/4 = 1M float4
    const int per_b = TQ * DD / 4;                    // 256K float4 per batch (old rows)
    const int total = BB * per_b;
    if (i >= total) return;
    int b = i / per_b;
    int rem = i - b * per_b;
    size_t idx = (size_t)b * (TKV * DD / 4) + rem;    // same offset in src and dst
    kdst[idx] = ksrc[idx];
    vdst[idx] = vsrc[idx];
}

// ---------------------------------------------------------------------------
// NT GEMM:  C[m,n] = sum_k A[m,k] * W[n,k]  (+ bias[n]),  M=4096, N=1024, K=1024
// mode 0: A=x, W=Wq, +bq, store (acc)*0.125 -> g_q            (scale^2 fold)
// mode 1: A=x, W=Wk,       store -> kout[b, TQ+t, n]
// mode 2: A=x, W=Wv, +bv,  store -> vout[b, TQ+t, n]
// mode 3: A=g_wv, W=Wo, +bo, store -> out[m, n]
// ---------------------------------------------------------------------------
__global__ __launch_bounds__(256) void gemm_nt(
    const float* __restrict__ X,
    const float* __restrict__ Wq, const float* __restrict__ bq,
    const float* __restrict__ Wk,
    const float* __restrict__ Wv, const float* __restrict__ bvv,
    const float* __restrict__ Wo, const float* __restrict__ bo,
    float* __restrict__ kout, float* __restrict__ vout,
    float* __restrict__ outp,
    int mode_base) {
    const int mode = mode_base + blockIdx.z;

    const float* A;
    const float* W;
    const float* bias;
    if (mode == 0)      { A = X;    W = Wq; bias = bq;  }
    else if (mode == 1) { A = X;    W = Wk; bias = 0;   }
    else if (mode == 2) { A = X;    W = Wv; bias = bvv; }
    else                { A = g_wv; W = Wo; bias = bo;  }

    __shared__ float As[BK][BM];
    __shared__ float Bs[BK][BN];

    const int tid = threadIdx.x;
    const int tx = tid & 15;       // N direction
    const int ty = tid >> 4;       // M direction
    const int m0 = blockIdx.y * BM;
    const int n0 = blockIdx.x * BN;

    const int lr  = tid >> 2;           // 0..63 tile row for loading
    const int lk4 = (tid & 3) << 2;     // k offset (float4)

    float acc[4][4];
#pragma unroll
    for (int i = 0; i < 4; i++)
#pragma unroll
        for (int j = 0; j < 4; j++) acc[i][j] = 0.f;

    for (int k0 = 0; k0 < DD; k0 += BK) {
        float4 av = *(const float4*)(A + (size_t)(m0 + lr) * DD + k0 + lk4);
        float4 bw = *(const float4*)(W + (size_t)(n0 + lr) * DD + k0 + lk4);
        As[lk4 + 0][lr] = av.x; As[lk4 + 1][lr] = av.y;
        As[lk4 + 2][lr] = av.z; As[lk4 + 3][lr] = av.w;
        Bs[lk4 + 0][lr] = bw.x; Bs[lk4 + 1][lr] = bw.y;
        Bs[lk4 + 2][lr] = bw.z; Bs[lk4 + 3][lr] = bw.w;
        __syncthreads();

#pragma unroll
        for (int kk = 0; kk < BK; kk++) {
            float4 a4 = *(const float4*)&As[kk][ty << 2];
            float4 b4 = *(const float4*)&Bs[kk][tx << 2];
            float ar[4] = {a4.x, a4.y, a4.z, a4.w};
            float br[4] = {b4.x, b4.y, b4.z, b4.w};
#pragma unroll
            for (int i = 0; i < 4; i++)
#pragma unroll
                for (int j = 0; j < 4; j++)
                    acc[i][j] = fmaf(ar[i], br[j], acc[i][j]);
        }
        __syncthreads();
    }

    // epilogue
#pragma unroll
    for (int i = 0; i < 4; i++) {
        int row = m0 + (ty << 2) + i;
#pragma unroll
        for (int j = 0; j < 4; j++) {
            int col = n0 + (tx << 2) + j;
            float v = acc[i][j];
            if (bias) v += bias[col];
            if (mode == 0) {
                g_q[(size_t)row * DD + col] = v * 0.125f;   // scale^2 = 1/sqrt(DH)
            } else if (mode == 3) {
                outp[(size_t)row * DD + col] = v;
            } else {
                int b = row >> 10;            // row / TQ
                int t = row & (TQ - 1);
                size_t di = (size_t)b * TKV * DD + (size_t)(TQ + t) * DD + col;
                if (mode == 1) kout[di] = v; else vout[di] = v;
            }
        }
    }
}

// ---------------------------------------------------------------------------
// Flash attention, fp32. One thread per query row; block = 128 queries of one
// (b, h). K/V tiles of 32 rows x 64 cols staged in smem, broadcast-read.
// ---------------------------------------------------------------------------
__global__ __launch_bounds__(128) void attn_kernel(
    const float* __restrict__ kc,    // [B, TKV, D] (final cache, in d_out)
    const float* __restrict__ vc,
    const float* __restrict__ mask)  // [TQ, TKV]
{
    __shared__ float4 Ks[32][16];
    __shared__ float4 Vs[32][16];

    const int tid = threadIdx.x;
    const int h = blockIdx.y;
    const int b = blockIdx.z;
    const int qrow = blockIdx.x * 128 + tid;     // 0..TQ-1

    const float* qptr = g_q + ((size_t)(b * TQ + qrow)) * DD + h * DHD;
    float4 qv[16];
#pragma unroll
    for (int c = 0; c < 16; c++) qv[c] = ((const float4*)qptr)[c];

    float4 o[16];
#pragma unroll
    for (int c = 0; c < 16; c++) o[c] = make_float4(0.f, 0.f, 0.f, 0.f);
    float m_run = -INFINITY, l_run = 0.f;

    const float* kb = kc + (size_t)b * TKV * DD + h * DHD;
    const float* vb = vc + (size_t)b * TKV * DD + h * DHD;
    const float* mrow = mask + (size_t)qrow * TKV;

    for (int kv0 = 0; kv0 < TKV; kv0 += 32) {
        __syncthreads();
#pragma unroll
        for (int it = 0; it < 4; it++) {
            int idx = tid + it * 128;            // 0..511
            int r = idx >> 4, c = idx & 15;
            Ks[r][c] = *(const float4*)(kb + (size_t)(kv0 + r) * DD + (c << 2));
            Vs[r][c] = *(const float4*)(vb + (size_t)(kv0 + r) * DD + (c << 2));
        }
        __syncthreads();

        float sv[32];
        float tmax = -INFINITY;
#pragma unroll
        for (int r = 0; r < 32; r++) {
            float s = 0.f;
#pragma unroll
            for (int c = 0; c < 16; c++) {
                float4 k4 = Ks[r][c];
                s = fmaf(qv[c].x, k4.x, s);
                s = fmaf(qv[c].y, k4.y, s);
                s = fmaf(qv[c].z, k4.z, s);
                s = fmaf(qv[c].w, k4.w, s);
            }
            s += mrow[kv0 + r];
            sv[r] = s;
            tmax = fmaxf(tmax, s);
        }

        float mnew = fmaxf(m_run, tmax);
        float corr = __expf(m_run - mnew);
        l_run *= corr;
#pragma unroll
        for (int c = 0; c < 16; c++) {
            o[c].x *= corr; o[c].y *= corr; o[c].z *= corr; o[c].w *= corr;
        }
#pragma unroll
        for (int r = 0; r < 32; r++) {
            float p = __expf(sv[r] - mnew);
            l_run += p;
#pragma unroll
            for (int c = 0; c < 16; c++) {
                float4 v4 = Vs[r][c];
                o[c].x = fmaf(p, v4.x, o[c].x);
                o[c].y = fmaf(p, v4.y, o[c].y);
                o[c].z = fmaf(p, v4.z, o[c].z);
                o[c].w = fmaf(p, v4.w, o[c].w);
            }
        }
        m_run = mnew;
    }

    float inv = 1.f / l_run;
    float* optr = g_wv + ((size_t)(b * TQ + qrow)) * DD + h * DHD;
#pragma unroll
    for (int c = 0; c < 16; c++) {
        float4 v = o[c];
        v.x *= inv; v.y *= inv; v.z *= inv; v.w *= inv;
        ((float4*)optr)[c] = v;
    }
}

// ---------------------------------------------------------------------------
// Launch
// ---------------------------------------------------------------------------
extern "C" void kernel_launch(void* const* d_in, const int* in_sizes, int n_in,
                              void* d_out, int out_size) {
    const float* x       = (const float*)d_in[0];
    const float* k_cache = (const float*)d_in[1];
    const float* v_cache = (const float*)d_in[2];
    const float* mask    = (const float*)d_in[3];
    const float* Wq      = (const float*)d_in[4];
    const float* bq      = (const float*)d_in[5];
    const float* Wk      = (const float*)d_in[6];
    const float* Wv      = (const float*)d_in[7];
    const float* bv      = (const float*)d_in[8];
    const float* Wo      = (const float*)d_in[9];
    const float* bo      = (const float*)d_in[10];

    float* outp = (float*)d_out;                          // [B, TQ, D]
    float* kout = outp + (size_t)BB * TQ * DD;            // [B, TKV, D]
    float* vout = kout + (size_t)BB * TKV * DD;           // [B, TKV, D]

    // 1) copy old cache rows (identity offsets)
    {
        int n4 = BB * TQ * DD / 4;
        copy_old_cache<<<(n4 + 255) / 256, 256>>>(
            (const float4*)k_cache, (const float4*)v_cache,
            (float4*)kout, (float4*)vout);
    }

    // 2) fused QKV projections (q scaled by 1/8 into g_q; k/v appended to caches)
    gemm_nt<<<dim3(DD / BN, (BB * TQ) / BM, 3), 256>>>(
        x, Wq, bq, Wk, Wv, bv, Wo, bo, kout, vout, outp, 0);

    // 3) attention -> g_wv
    attn_kernel<<<dim3(TQ / 128, HH, BB), 128>>>(kout, vout, mask);

    // 4) output projection
    gemm_nt<<<dim3(DD / BN, (BB * TQ) / BM, 1), 256>>>(
        x, Wq, bq, Wk, Wv, bv, Wo, bo, kout, vout, outp, 3);
}

// round 4
// speedup vs baseline: 3.7802x; 3.7802x over previous
#include <cuda_runtime.h>
#include <cuda_bf16.h>
#include <cstdint>
#include <math.h>

#define BB 4
#define TQ 1024
#define TKV 2048
#define DD 1024
#define HH 16
#define DHD 64

// ---------------- device scratch (static; no allocations) -------------------
__device__ __nv_bfloat16 g_xh[BB*TQ*DD],  g_xl[BB*TQ*DD];
__device__ __nv_bfloat16 g_Wqh[DD*DD], g_Wql[DD*DD];
__device__ __nv_bfloat16 g_Wkh[DD*DD], g_Wkl[DD*DD];
__device__ __nv_bfloat16 g_Wvh[DD*DD], g_Wvl[DD*DD];
__device__ __nv_bfloat16 g_Woh[DD*DD], g_Wol[DD*DD];
__device__ __nv_bfloat16 g_qh[BB*TQ*DD],  g_ql[BB*TQ*DD];    // [b,h,tq,64], x0.125
__device__ __nv_bfloat16 g_kh[BB*TKV*DD], g_kl[BB*TKV*DD];   // [b,h,kv,64]
__device__ __nv_bfloat16 g_vth[BB*TKV*DD], g_vtl[BB*TKV*DD]; // [b,h,64,kv]
__device__ __nv_bfloat16 g_avh[BB*TQ*DD], g_avl[BB*TQ*DD];   // attn out [m,1024]

// ---------------- helpers ---------------------------------------------------
__device__ __forceinline__ uint32_t smem_u32(const void* p){
    uint32_t a;
    asm("{ .reg .u64 t; cvta.to.shared.u64 t, %1; cvt.u32.u64 %0, t; }" : "=r"(a) : "l"(p));
    return a;
}
#define SW128(o) ((o) ^ (((o) >> 3) & 0x70))

__device__ __forceinline__ void ldm4(uint32_t* r, uint32_t addr){
    asm volatile("ldmatrix.sync.aligned.m8n8.x4.shared.b16 {%0,%1,%2,%3}, [%4];"
        : "=r"(r[0]), "=r"(r[1]), "=r"(r[2]), "=r"(r[3]) : "r"(addr));
}
__device__ __forceinline__ void mma_bf(float* c, const uint32_t* a, uint32_t b0, uint32_t b1){
    asm volatile("mma.sync.aligned.m16n8k16.row.col.f32.bf16.bf16.f32 "
        "{%0,%1,%2,%3}, {%4,%5,%6,%7}, {%8,%9}, {%0,%1,%2,%3};"
        : "+f"(c[0]), "+f"(c[1]), "+f"(c[2]), "+f"(c[3])
        : "r"(a[0]), "r"(a[1]), "r"(a[2]), "r"(a[3]), "r"(b0), "r"(b1));
}
__device__ __forceinline__ void cp16(uint32_t dst, const void* src){
    asm volatile("cp.async.cg.shared.global [%0], [%1], 16;" :: "r"(dst), "l"(src));
}
#define CP_COMMIT() asm volatile("cp.async.commit_group;")
__device__ __forceinline__ void sts128(uint32_t addr, uint4 v){
    asm volatile("st.shared.v4.b32 [%0], {%1,%2,%3,%4};"
        :: "r"(addr), "r"(v.x), "r"(v.y), "r"(v.z), "r"(v.w));
}
__device__ __forceinline__ void sts32(uint32_t addr, uint32_t v){
    asm volatile("st.shared.b32 [%0], %1;" :: "r"(addr), "r"(v));
}
__device__ __forceinline__ void split2(float x, __nv_bfloat16& h, __nv_bfloat16& l){
    h = __float2bfloat16(x);
    l = __float2bfloat16(x - __bfloat162float(h));
}
__device__ __forceinline__ uint32_t bf2u(__nv_bfloat162 v){
    return *reinterpret_cast<uint32_t*>(&v);
}

// ---------------- small prep kernels ---------------------------------------
__global__ void copy_old_cache(const float4* __restrict__ ksrc,
                               const float4* __restrict__ vsrc,
                               float4* __restrict__ kdst,
                               float4* __restrict__ vdst){
    int i = blockIdx.x * blockDim.x + threadIdx.x;
    const int per_b = TQ * DD / 4;
    if (i >= BB * per_b) return;
    int b = i / per_b;
    int rem = i - b * per_b;
    size_t idx = (size_t)b * (TKV * DD / 4) + rem;
    kdst[idx] = ksrc[idx];
    vdst[idx] = vsrc[idx];
}

__global__ void conv_split(const float4* __restrict__ src, int which, int n4){
    int i = blockIdx.x * blockDim.x + threadIdx.x;
    if (i >= n4) return;
    __nv_bfloat16 *H, *L;
    switch (which){
        case 0: H = g_xh;  L = g_xl;  break;
        case 1: H = g_Wqh; L = g_Wql; break;
        case 2: H = g_Wkh; L = g_Wkl; break;
        case 3: H = g_Wvh; L = g_Wvl; break;
        default:H = g_Woh; L = g_Wol; break;
    }
    float4 v = src[i];
    float vs[4] = {v.x, v.y, v.z, v.w};
    __nv_bfloat16 hh[4], ll[4];
#pragma unroll
    for (int j = 0; j < 4; j++) split2(vs[j], hh[j], ll[j]);
    ((__nv_bfloat162*)H)[i*2+0] = __halves2bfloat162(hh[0], hh[1]);
    ((__nv_bfloat162*)H)[i*2+1] = __halves2bfloat162(hh[2], hh[3]);
    ((__nv_bfloat162*)L)[i*2+0] = __halves2bfloat162(ll[0], ll[1]);
    ((__nv_bfloat162*)L)[i*2+1] = __halves2bfloat162(ll[2], ll[3]);
}

// K cache [b,kv,D] fp32 -> head-major bf16 hi/lo [b,h,kv,64]
__global__ void kconv(const float4* __restrict__ kc){
    int i = blockIdx.x * blockDim.x + threadIdx.x;
    if (i >= BB*TKV*DD/4) return;
    int b = i >> 19;
    int rem = i & ((1 << 19) - 1);
    int kv = rem >> 8;
    int d = (rem & 255) * 4;
    int h = d >> 6, dh = d & 63;
    float4 v = kc[i];
    float vs[4] = {v.x, v.y, v.z, v.w};
    size_t o = (((size_t)b*HH + h)*TKV + kv)*64 + dh;
    __nv_bfloat16 hh[4], ll[4];
#pragma unroll
    for (int j = 0; j < 4; j++) split2(vs[j], hh[j], ll[j]);
    *(__nv_bfloat162*)(g_kh + o)     = __halves2bfloat162(hh[0], hh[1]);
    *(__nv_bfloat162*)(g_kh + o + 2) = __halves2bfloat162(hh[2], hh[3]);
    *(__nv_bfloat162*)(g_kl + o)     = __halves2bfloat162(ll[0], ll[1]);
    *(__nv_bfloat162*)(g_kl + o + 2) = __halves2bfloat162(ll[2], ll[3]);
}

// V cache [b,kv,D] fp32 -> transposed bf16 hi/lo [b,h,64,kv]
__global__ void vconv(const float* __restrict__ vc){
    __shared__ float t[128][65];
    int kv0 = blockIdx.x * 128, h = blockIdx.y, b = blockIdx.z;
    int tid = threadIdx.x;
    for (int i = tid; i < 128*16; i += 256){
        int r = i >> 4, c4 = i & 15;
        float4 v = *(const float4*)(vc + ((size_t)(b*TKV + kv0 + r))*DD + h*64 + c4*4);
        t[r][c4*4+0] = v.x; t[r][c4*4+1] = v.y; t[r][c4*4+2] = v.z; t[r][c4*4+3] = v.w;
    }
    __syncthreads();
    for (int i = tid; i < 64*128; i += 256){
        int dh = i >> 7, j = i & 127;
        float v = t[j][dh];
        __nv_bfloat16 hh, ll; split2(v, hh, ll);
        size_t o = (((size_t)b*HH + h)*64 + dh)*TKV + kv0 + j;
        g_vth[o] = hh; g_vtl[o] = ll;
    }
}

// ---------------- tensor-core (HMMA) projection GEMM -----------------------
// C[m,n] = sum_k A[m,k]*W[n,k] (+bias). M=4096, N=1024, K=1024.
// 128x128 block, 8 warps x (16 rows x 128 cols), BK=64, cp.async double buffer.
// smem: 2 stages x {Ah,Al,Bh,Bl} x 16KB = 131072 bytes
#define G_SMEM 131072

__global__ void __launch_bounds__(256, 1) gemm_tc(int mode_base,
    const float* __restrict__ bq, const float* __restrict__ bvv, const float* __restrict__ bo,
    float* __restrict__ kout, float* __restrict__ vout, float* __restrict__ outp){
    extern __shared__ char sm[];
    const int mode = mode_base + blockIdx.z;
    const __nv_bfloat16 *Ah, *Al, *Bh, *Bl;
    const float* bias;
    if (mode == 0)      { Ah=g_xh;  Al=g_xl;  Bh=g_Wqh; Bl=g_Wql; bias=bq;  }
    else if (mode == 1) { Ah=g_xh;  Al=g_xl;  Bh=g_Wkh; Bl=g_Wkl; bias=0;   }
    else if (mode == 2) { Ah=g_xh;  Al=g_xl;  Bh=g_Wvh; Bl=g_Wvl; bias=bvv; }
    else                { Ah=g_avh; Al=g_avl; Bh=g_Woh; Bl=g_Wol; bias=bo;  }

    uint32_t sb = smem_u32(sm);
    const int tid = threadIdx.x, wid = tid >> 5, lane = tid & 31;
    const int m0 = blockIdx.y * 128, n0 = blockIdx.x * 128;
    const int R0 = wid * 16;

    const __nv_bfloat16* srcs[4] = {
        Ah + (size_t)m0*DD, Al + (size_t)m0*DD,
        Bh + (size_t)n0*DD, Bl + (size_t)n0*DD };

    const int lr = tid >> 3, lkc = tid & 7;     // base row/chunk for loads

#define G_ISSUE(ch, buf) do { \
    int k0_ = (ch) * 64; \
    _Pragma("unroll") \
    for (int t2 = 0; t2 < 4; t2++){ \
        uint32_t base_ = sb + (buf)*65536 + t2*16384; \
        _Pragma("unroll") \
        for (int i_ = 0; i_ < 4; i_++){ \
            int r_ = lr + i_*32; \
            cp16(base_ + SW128((uint32_t)(r_*128 + lkc*16)), \
                 srcs[t2] + (size_t)r_*DD + k0_ + lkc*8); \
        } \
    } \
    CP_COMMIT(); \
} while (0)

    G_ISSUE(0, 0);
    G_ISSUE(1, 1);

    float acc[16][4];
#pragma unroll
    for (int i = 0; i < 16; i++)
#pragma unroll
        for (int j = 0; j < 4; j++) acc[i][j] = 0.f;

    const int ar  = R0 + (lane & 15);
    const int akh = lane >> 4;
    const int bi  = lane & 7;
    const int grp = lane >> 3;

    for (int ch = 0; ch < 16; ch++){
        if (ch == 15) asm volatile("cp.async.wait_group 0;" ::: "memory");
        else          asm volatile("cp.async.wait_group 1;" ::: "memory");
        __syncthreads();
        uint32_t ba = sb + (ch & 1) * 65536;
#pragma unroll
        for (int k16 = 0; k16 < 4; k16++){
            uint32_t aoff = SW128((uint32_t)(ar*128 + (k16*2 + akh)*16));
            uint32_t ah[4], al[4];
            ldm4(ah, ba + aoff);
            ldm4(al, ba + 16384 + aoff);
#pragma unroll
            for (int np = 0; np < 8; np++){
                int bn  = np*16 + (grp >> 1)*8 + bi;
                int bkc = k16*2 + (grp & 1);
                uint32_t boff = SW128((uint32_t)(bn*128 + bkc*16));
                uint32_t bh[4], bl[4];
                ldm4(bh, ba + 2*16384 + boff);
                ldm4(bl, ba + 3*16384 + boff);
                mma_bf(acc[np*2],   ah, bh[0], bh[1]);
                mma_bf(acc[np*2+1], ah, bh[2], bh[3]);
                mma_bf(acc[np*2],   ah, bl[0], bl[1]);
                mma_bf(acc[np*2+1], ah, bl[2], bl[3]);
                mma_bf(acc[np*2],   al, bh[0], bh[1]);
                mma_bf(acc[np*2+1], al, bh[2], bh[3]);
            }
        }
        __syncthreads();
        if (ch + 2 < 16) G_ISSUE(ch + 2, ch & 1);
    }
#undef G_ISSUE

    // epilogue
    const int r1 = m0 + R0 + (lane >> 2), r2 = r1 + 8;
#pragma unroll
    for (int nf = 0; nf < 16; nf++){
        int c = n0 + nf*8 + (lane & 3)*2;
        float v0 = acc[nf][0], v1 = acc[nf][1], v2 = acc[nf][2], v3 = acc[nf][3];
        if (bias){
            float2 bb = *(const float2*)(bias + c);
            v0 += bb.x; v1 += bb.y; v2 += bb.x; v3 += bb.y;
        }
        if (mode == 0){
            v0 *= 0.125f; v1 *= 0.125f; v2 *= 0.125f; v3 *= 0.125f;
            int h = c >> 6, dh = c & 63;
#pragma unroll
            for (int rr = 0; rr < 2; rr++){
                int row = rr ? r2 : r1;
                float a = rr ? v2 : v0, b2 = rr ? v3 : v1;
                int b = row >> 10, q = row & 1023;
                size_t o = (((size_t)b*HH + h)*TQ + q)*64 + dh;
                __nv_bfloat16 ha, la, hb, lb;
                split2(a, ha, la); split2(b2, hb, lb);
                *(__nv_bfloat162*)(g_qh + o) = __halves2bfloat162(ha, hb);
                *(__nv_bfloat162*)(g_ql + o) = __halves2bfloat162(la, lb);
            }
        } else if (mode == 3){
            *(float2*)(outp + (size_t)r1*DD + c) = make_float2(v0, v1);
            *(float2*)(outp + (size_t)r2*DD + c) = make_float2(v2, v3);
        } else {
            float* dst = (mode == 1) ? kout : vout;
#pragma unroll
            for (int rr = 0; rr < 2; rr++){
                int row = rr ? r2 : r1;
                int b = row >> 10, q = row & 1023;
                size_t o = ((size_t)b*TKV + TQ + q)*DD + c;
                *(float2*)(dst + o) = rr ? make_float2(v2, v3) : make_float2(v0, v1);
            }
        }
    }
}

// ---------------- attention (HMMA) ------------------------------------------
// per block: 128 q-rows of one (b,h). 8 warps x 16 rows. No online max
// (softmax shift-invariant; logits are O(1)); normalize by row sum at end.
#define A_QH 0
#define A_QL 16384
#define A_KH 32768
#define A_KL 49152
#define A_VH 65536
#define A_VL 81920
#define A_PH 98304
#define A_PL 131072
#define A_SMEM 163840

__global__ void __launch_bounds__(256, 1) attn_tc(const float* __restrict__ mask){
    extern __shared__ char sm[];
    uint32_t sb = smem_u32(sm);
    const int tid = threadIdx.x, wid = tid >> 5, lane = tid & 31;
    const int q0 = blockIdx.x * 128, h = blockIdx.y, b = blockIdx.z;
    const size_t bh = (size_t)b * HH + h;
    const int R0 = wid * 16;

    const __nv_bfloat16* Qbh = g_qh  + (bh*TQ + q0)*64;
    const __nv_bfloat16* Qbl = g_ql  + (bh*TQ + q0)*64;
    const __nv_bfloat16* Kbh = g_kh  + bh * (size_t)TKV * 64;
    const __nv_bfloat16* Kbl = g_kl  + bh * (size_t)TKV * 64;
    const __nv_bfloat16* Vbh = g_vth + bh * (size_t)64 * TKV;
    const __nv_bfloat16* Vbl = g_vtl + bh * (size_t)64 * TKV;

    // load Q (contiguous 16KB per half)
#pragma unroll
    for (int i = 0; i < 4; i++){
        int f = i*256 + tid, r = f >> 3, kc = f & 7;
        uint32_t d = SW128((uint32_t)(r*128 + kc*16));
        sts128(sb + A_QH + d, *(const uint4*)(Qbh + f*8));
        sts128(sb + A_QL + d, *(const uint4*)(Qbl + f*8));
    }

    float Oacc[8][4];
#pragma unroll
    for (int i = 0; i < 8; i++)
#pragma unroll
        for (int j = 0; j < 4; j++) Oacc[i][j] = 0.f;
    float rs0 = 0.f, rs1 = 0.f;

    const int r1l = R0 + (lane >> 2), r2l = r1l + 8;
    const int ar  = R0 + (lane & 15);
    const int akh = lane >> 4;
    const int bi  = lane & 7;
    const int grp = lane >> 3;
    const float* m1 = mask + (size_t)(q0 + r1l)*TKV + (lane & 3)*2;
    const float* m2 = m1 + 8*TKV;

    for (int it = 0; it < 16; it++){
        int kv0 = it * 128;
        __syncthreads();   // prior tile's reads of K/V done
        // load K tile (contiguous) and Vt tile (rows stride TKV)
#pragma unroll
        for (int i = 0; i < 4; i++){
            int f = i*256 + tid;
            { int r = f >> 3, kc = f & 7;
              uint32_t d = SW128((uint32_t)(r*128 + kc*16));
              const __nv_bfloat16* s = Kbh + (size_t)kv0*64 + f*8;
              const __nv_bfloat16* s2 = Kbl + (size_t)kv0*64 + f*8;
              sts128(sb + A_KH + d, *(const uint4*)s);
              sts128(sb + A_KL + d, *(const uint4*)s2); }
            { int r = f >> 4, kc = f & 15;
              uint32_t d = (uint32_t)(r*256 + ((kc >> 3) << 7) + (((kc & 7) ^ (r & 7)) << 4));
              sts128(sb + A_VH + d, *(const uint4*)(Vbh + (size_t)r*TKV + kv0 + kc*8));
              sts128(sb + A_VL + d, *(const uint4*)(Vbl + (size_t)r*TKV + kv0 + kc*8)); }
        }
        __syncthreads();

        // S = Q K^T  (128 x 128), 3-pass split
        float Sacc[16][4];
#pragma unroll
        for (int i = 0; i < 16; i++)
#pragma unroll
            for (int j = 0; j < 4; j++) Sacc[i][j] = 0.f;
#pragma unroll
        for (int k16 = 0; k16 < 4; k16++){
            uint32_t aoff = SW128((uint32_t)(ar*128 + (k16*2 + akh)*16));
            uint32_t qh[4], ql[4];
            ldm4(qh, sb + A_QH + aoff);
            ldm4(ql, sb + A_QL + aoff);
#pragma unroll
            for (int np = 0; np < 8; np++){
                int bn  = np*16 + (grp >> 1)*8 + bi;
                int bkc = k16*2 + (grp & 1);
                uint32_t boff = SW128((uint32_t)(bn*128 + bkc*16));
                uint32_t kh[4], kl[4];
                ldm4(kh, sb + A_KH + boff);
                ldm4(kl, sb + A_KL + boff);
                mma_bf(Sacc[np*2],   qh, kh[0], kh[1]);
                mma_bf(Sacc[np*2+1], qh, kh[2], kh[3]);
                mma_bf(Sacc[np*2],   qh, kl[0], kl[1]);
                mma_bf(Sacc[np*2+1], qh, kl[2], kl[3]);
                mma_bf(Sacc[np*2],   ql, kh[0], kh[1]);
                mma_bf(Sacc[np*2+1], ql, kh[2], kh[3]);
            }
        }

        // P = exp(S + mask); accumulate row sums; store P hi/lo to smem
#pragma unroll
        for (int nf = 0; nf < 16; nf++){
            float2 ma = *(const float2*)(m1 + kv0 + nf*8);
            float2 mb = *(const float2*)(m2 + kv0 + nf*8);
            float p0 = __expf(Sacc[nf][0] + ma.x);
            float p1 = __expf(Sacc[nf][1] + ma.y);
            float p2 = __expf(Sacc[nf][2] + mb.x);
            float p3 = __expf(Sacc[nf][3] + mb.y);
            rs0 += p0 + p1; rs1 += p2 + p3;
            __nv_bfloat162 h01 = __floats2bfloat162_rn(p0, p1);
            __nv_bfloat162 l01 = __floats2bfloat162_rn(p0 - __low2float(h01), p1 - __high2float(h01));
            __nv_bfloat162 h23 = __floats2bfloat162_rn(p2, p3);
            __nv_bfloat162 l23 = __floats2bfloat162_rn(p2 - __low2float(h23), p3 - __high2float(h23));
            uint32_t o1 = (uint32_t)(r1l*256 + ((nf >> 3) << 7) + (((nf & 7) ^ (r1l & 7)) << 4) + (lane & 3)*4);
            uint32_t o2 = (uint32_t)(r2l*256 + ((nf >> 3) << 7) + (((nf & 7) ^ (r2l & 7)) << 4) + (lane & 3)*4);
            sts32(sb + A_PH + o1, bf2u(h01));
            sts32(sb + A_PL + o1, bf2u(l01));
            sts32(sb + A_PH + o2, bf2u(h23));
            sts32(sb + A_PL + o2, bf2u(l23));
        }
        __syncwarp();   // P rows are warp-private; warp-level visibility suffices

        // O += P V^T  (128 x 64 over k=128), 3-pass split
#pragma unroll
        for (int k16 = 0; k16 < 8; k16++){
            int pkc = k16*2 + akh;
            uint32_t poff = (uint32_t)(ar*256 + ((pkc >> 3) << 7) + (((pkc & 7) ^ (ar & 7)) << 4));
            uint32_t ph[4], pl[4];
            ldm4(ph, sb + A_PH + poff);
            ldm4(pl, sb + A_PL + poff);
#pragma unroll
            for (int np = 0; np < 4; np++){
                int vn  = np*16 + (grp >> 1)*8 + bi;
                int vkc = k16*2 + (grp & 1);
                uint32_t voff = (uint32_t)(vn*256 + ((vkc >> 3) << 7) + (((vkc & 7) ^ (vn & 7)) << 4));
                uint32_t vh[4], vl[4];
                ldm4(vh, sb + A_VH + voff);
                ldm4(vl, sb + A_VL + voff);
                mma_bf(Oacc[np*2],   ph, vh[0], vh[1]);
                mma_bf(Oacc[np*2+1], ph, vh[2], vh[3]);
                mma_bf(Oacc[np*2],   ph, vl[0], vl[1]);
                mma_bf(Oacc[np*2+1], ph, vl[2], vl[3]);
                mma_bf(Oacc[np*2],   pl, vh[0], vh[1]);
                mma_bf(Oacc[np*2+1], pl, vh[2], vh[3]);
            }
        }
    }

    // row-sum reduce across the 4 lanes sharing each row
    rs0 += __shfl_xor_sync(0xffffffffu, rs0, 1);
    rs0 += __shfl_xor_sync(0xffffffffu, rs0, 2);
    rs1 += __shfl_xor_sync(0xffffffffu, rs1, 1);
    rs1 += __shfl_xor_sync(0xffffffffu, rs1, 2);
    float inv0 = 1.f / rs0, inv1 = 1.f / rs1;

    // normalize + split + write attention output (head-major cols of [m,1024])
    size_t base1 = ((size_t)(b*TQ + q0 + r1l))*DD + h*64;
    size_t base2 = ((size_t)(b*TQ + q0 + r2l))*DD + h*64;
#pragma unroll
    for (int nf = 0; nf < 8; nf++){
        int c = nf*8 + (lane & 3)*2;
        float v0 = Oacc[nf][0]*inv0, v1 = Oacc[nf][1]*inv0;
        float v2 = Oacc[nf][2]*inv1, v3 = Oacc[nf][3]*inv1;
        __nv_bfloat16 ha, la, hb, lb;
        split2(v0, ha, la); split2(v1, hb, lb);
        *(__nv_bfloat162*)(g_avh + base1 + c) = __halves2bfloat162(ha, hb);
        *(__nv_bfloat162*)(g_avl + base1 + c) = __halves2bfloat162(la, lb);
        split2(v2, ha, la); split2(v3, hb, lb);
        *(__nv_bfloat162*)(g_avh + base2 + c) = __halves2bfloat162(ha, hb);
        *(__nv_bfloat162*)(g_avl + base2 + c) = __halves2bfloat162(la, lb);
    }
}

// ---------------- launch ----------------------------------------------------
extern "C" void kernel_launch(void* const* d_in, const int* in_sizes, int n_in,
                              void* d_out, int out_size) {
    const float* x       = (const float*)d_in[0];
    const float* k_cache = (const float*)d_in[1];
    const float* v_cache = (const float*)d_in[2];
    const float* mask    = (const float*)d_in[3];
    const float* Wq      = (const float*)d_in[4];
    const float* bq      = (const float*)d_in[5];
    const float* Wk      = (const float*)d_in[6];
    const float* Wv      = (const float*)d_in[7];
    const float* bv      = (const float*)d_in[8];
    const float* Wo      = (const float*)d_in[9];
    const float* bo      = (const float*)d_in[10];

    float* outp = (float*)d_out;
    float* kout = outp + (size_t)BB * TQ * DD;
    float* vout = kout + (size_t)BB * TKV * DD;

    static int attr_done = 0;
    if (!attr_done){
        cudaFuncSetAttribute(gemm_tc, cudaFuncAttributeMaxDynamicSharedMemorySize, G_SMEM);
        cudaFuncSetAttribute(attn_tc, cudaFuncAttributeMaxDynamicSharedMemorySize, A_SMEM);
        attr_done = 1;
    }

    // 1) old cache rows -> output
    {
        int n4 = BB * TQ * DD / 4;
        copy_old_cache<<<(n4 + 255)/256, 256>>>(
            (const float4*)k_cache, (const float4*)v_cache,
            (float4*)kout, (float4*)vout);
    }
    // 2) bf16 hi/lo conversions of x and weights
    conv_split<<<(BB*TQ*DD/4 + 255)/256, 256>>>((const float4*)x,  0, BB*TQ*DD/4);
    conv_split<<<(DD*DD/4 + 255)/256, 256>>>((const float4*)Wq, 1, DD*DD/4);
    conv_split<<<(DD*DD/4 + 255)/256, 256>>>((const float4*)Wk, 2, DD*DD/4);
    conv_split<<<(DD*DD/4 + 255)/256, 256>>>((const float4*)Wv, 3, DD*DD/4);
    conv_split<<<(DD*DD/4 + 255)/256, 256>>>((const float4*)Wo, 4, DD*DD/4);
    // 3) QKV projections
    gemm_tc<<<dim3(DD/128, BB*TQ/128, 3), 256, G_SMEM>>>(0, bq, bv, bo, kout, vout, outp);
    // 4) K/V cache -> bf16 hi/lo operand layouts
    kconv<<<(BB*TKV*DD/4 + 255)/256, 256>>>((const float4*)kout);
    vconv<<<dim3(TKV/128, HH, BB), 256>>>(vout);
    // 5) attention
    attn_tc<<<dim3(TQ/128, HH, BB), 256, A_SMEM>>>(mask);
    // 6) output projection
    gemm_tc<<<dim3(DD/128, BB*TQ/128, 1), 256, G_SMEM>>>(3, bq, bv, bo, kout, vout, outp);
}

// round 5
// speedup vs baseline: 4.0446x; 1.0700x over previous
#include <cuda_runtime.h>
#include <cuda_bf16.h>
#include <cstdint>
#include <math.h>

#define BB 4
#define TQ 1024
#define TKV 2048
#define DD 1024
#define HH 16
#define DHD 64

// ---------------- device scratch (static; no allocations) -------------------
__device__ __nv_bfloat16 g_xh[BB*TQ*DD],  g_xl[BB*TQ*DD];
__device__ __nv_bfloat16 g_Wqh[DD*DD], g_Wql[DD*DD];
__device__ __nv_bfloat16 g_Wkh[DD*DD], g_Wkl[DD*DD];
__device__ __nv_bfloat16 g_Wvh[DD*DD], g_Wvl[DD*DD];
__device__ __nv_bfloat16 g_Woh[DD*DD], g_Wol[DD*DD];
__device__ __nv_bfloat16 g_qh[BB*TQ*DD],  g_ql[BB*TQ*DD];    // [b,h,tq,64], x0.125
__device__ __nv_bfloat16 g_kh[BB*TKV*DD], g_kl[BB*TKV*DD];   // [b,h,kv,64]
__device__ __nv_bfloat16 g_vth[BB*TKV*DD], g_vtl[BB*TKV*DD]; // [b,h,64,kv]
__device__ __nv_bfloat16 g_avh[BB*TQ*DD], g_avl[BB*TQ*DD];   // attn out [m,1024]

// ---------------- helpers ---------------------------------------------------
__device__ __forceinline__ uint32_t smem_u32(const void* p){
    uint32_t a;
    asm("{ .reg .u64 t; cvta.to.shared.u64 t, %1; cvt.u32.u64 %0, t; }" : "=r"(a) : "l"(p));
    return a;
}
#define SW128(o) ((o) ^ (((o) >> 3) & 0x70))

__device__ __forceinline__ void ldm4(uint32_t* r, uint32_t addr){
    asm volatile("ldmatrix.sync.aligned.m8n8.x4.shared.b16 {%0,%1,%2,%3}, [%4];"
        : "=r"(r[0]), "=r"(r[1]), "=r"(r[2]), "=r"(r[3]) : "r"(addr));
}
__device__ __forceinline__ void mma_bf(float* c, const uint32_t* a, uint32_t b0, uint32_t b1){
    asm volatile("mma.sync.aligned.m16n8k16.row.col.f32.bf16.bf16.f32 "
        "{%0,%1,%2,%3}, {%4,%5,%6,%7}, {%8,%9}, {%0,%1,%2,%3};"
        : "+f"(c[0]), "+f"(c[1]), "+f"(c[2]), "+f"(c[3])
        : "r"(a[0]), "r"(a[1]), "r"(a[2]), "r"(a[3]), "r"(b0), "r"(b1));
}
__device__ __forceinline__ void cp16(uint32_t dst, const void* src){
    asm volatile("cp.async.cg.shared.global [%0], [%1], 16;" :: "r"(dst), "l"(src));
}
#define CP_COMMIT() asm volatile("cp.async.commit_group;")
__device__ __forceinline__ void sts128(uint32_t addr, uint4 v){
    asm volatile("st.shared.v4.b32 [%0], {%1,%2,%3,%4};"
        :: "r"(addr), "r"(v.x), "r"(v.y), "r"(v.z), "r"(v.w));
}
__device__ __forceinline__ void sts32(uint32_t addr, uint32_t v){
    asm volatile("st.shared.b32 [%0], %1;" :: "r"(addr), "r"(v));
}
__device__ __forceinline__ void split2(float x, __nv_bfloat16& h, __nv_bfloat16& l){
    h = __float2bfloat16(x);
    l = __float2bfloat16(x - __bfloat162float(h));
}
__device__ __forceinline__ uint32_t bf2u(__nv_bfloat162 v){
    return *reinterpret_cast<uint32_t*>(&v);
}

// ---------------- small prep kernels ---------------------------------------
// old cache rows -> output caches; ALSO emit K bf16 hi/lo head-major operands
__global__ void copy_old_cache(const float4* __restrict__ ksrc,
                               const float4* __restrict__ vsrc,
                               float4* __restrict__ kdst,
                               float4* __restrict__ vdst){
    int i = blockIdx.x * blockDim.x + threadIdx.x;
    const int per_b = TQ * DD / 4;
    if (i >= BB * per_b) return;
    int b = i / per_b;
    int rem = i - b * per_b;
    size_t idx = (size_t)b * (TKV * DD / 4) + rem;
    float4 kv4 = ksrc[idx];
    kdst[idx] = kv4;
    vdst[idx] = vsrc[idx];
    // K operand conversion: rem = t*256 + c4 ; d = c4*4
    int t = rem >> 8;
    int d = (rem & 255) * 4;
    int h = d >> 6, dh = d & 63;
    float vs[4] = {kv4.x, kv4.y, kv4.z, kv4.w};
    __nv_bfloat16 hh[4], ll[4];
#pragma unroll
    for (int j = 0; j < 4; j++) split2(vs[j], hh[j], ll[j]);
    size_t o = (((size_t)b*HH + h)*TKV + t)*64 + dh;
    *(__nv_bfloat162*)(g_kh + o)     = __halves2bfloat162(hh[0], hh[1]);
    *(__nv_bfloat162*)(g_kh + o + 2) = __halves2bfloat162(hh[2], hh[3]);
    *(__nv_bfloat162*)(g_kl + o)     = __halves2bfloat162(ll[0], ll[1]);
    *(__nv_bfloat162*)(g_kl + o + 2) = __halves2bfloat162(ll[2], ll[3]);
}

__global__ void conv_split(const float4* __restrict__ src, int which, int n4){
    int i = blockIdx.x * blockDim.x + threadIdx.x;
    if (i >= n4) return;
    __nv_bfloat16 *H, *L;
    switch (which){
        case 0: H = g_xh;  L = g_xl;  break;
        case 1: H = g_Wqh; L = g_Wql; break;
        case 2: H = g_Wkh; L = g_Wkl; break;
        case 3: H = g_Wvh; L = g_Wvl; break;
        default:H = g_Woh; L = g_Wol; break;
    }
    float4 v = src[i];
    float vs[4] = {v.x, v.y, v.z, v.w};
    __nv_bfloat16 hh[4], ll[4];
#pragma unroll
    for (int j = 0; j < 4; j++) split2(vs[j], hh[j], ll[j]);
    ((__nv_bfloat162*)H)[i*2+0] = __halves2bfloat162(hh[0], hh[1]);
    ((__nv_bfloat162*)H)[i*2+1] = __halves2bfloat162(hh[2], hh[3]);
    ((__nv_bfloat162*)L)[i*2+0] = __halves2bfloat162(ll[0], ll[1]);
    ((__nv_bfloat162*)L)[i*2+1] = __halves2bfloat162(ll[2], ll[3]);
}

// V cache [b,kv,D] fp32 -> transposed bf16 hi/lo [b,h,64,kv]
__global__ void vconv(const float* __restrict__ vc){
    __shared__ float t[128][65];
    int kv0 = blockIdx.x * 128, h = blockIdx.y, b = blockIdx.z;
    int tid = threadIdx.x;
    for (int i = tid; i < 128*16; i += 256){
        int r = i >> 4, c4 = i & 15;
        float4 v = *(const float4*)(vc + ((size_t)(b*TKV + kv0 + r))*DD + h*64 + c4*4);
        t[r][c4*4+0] = v.x; t[r][c4*4+1] = v.y; t[r][c4*4+2] = v.z; t[r][c4*4+3] = v.w;
    }
    __syncthreads();
    for (int i = tid; i < 64*128; i += 256){
        int dh = i >> 7, j = i & 127;
        float v = t[j][dh];
        __nv_bfloat16 hh, ll; split2(v, hh, ll);
        size_t o = (((size_t)b*HH + h)*64 + dh)*TKV + kv0 + j;
        g_vth[o] = hh; g_vtl[o] = ll;
    }
}

// ---------------- tensor-core (HMMA) projection GEMM -----------------------
// C[m,n] = sum_k A[m,k]*W[n,k] (+bias). M=4096, N=1024, K=1024.
// 128x128 block, 8 warps x (16 rows x 128 cols), BK=64, cp.async double buffer.
#define G_SMEM 131072

__global__ void __launch_bounds__(256, 1) gemm_tc(int mode_base,
    const float* __restrict__ bq, const float* __restrict__ bvv, const float* __restrict__ bo,
    float* __restrict__ kout, float* __restrict__ vout, float* __restrict__ outp){
    extern __shared__ char sm[];
    const int mode = mode_base + blockIdx.z;
    const __nv_bfloat16 *Ah, *Al, *Bh, *Bl;
    const float* bias;
    if (mode == 0)      { Ah=g_xh;  Al=g_xl;  Bh=g_Wqh; Bl=g_Wql; bias=bq;  }
    else if (mode == 1) { Ah=g_xh;  Al=g_xl;  Bh=g_Wkh; Bl=g_Wkl; bias=0;   }
    else if (mode == 2) { Ah=g_xh;  Al=g_xl;  Bh=g_Wvh; Bl=g_Wvl; bias=bvv; }
    else                { Ah=g_avh; Al=g_avl; Bh=g_Woh; Bl=g_Wol; bias=bo;  }

    uint32_t sb = smem_u32(sm);
    const int tid = threadIdx.x, wid = tid >> 5, lane = tid & 31;
    const int m0 = blockIdx.y * 128, n0 = blockIdx.x * 128;
    const int R0 = wid * 16;

    const __nv_bfloat16* srcs[4] = {
        Ah + (size_t)m0*DD, Al + (size_t)m0*DD,
        Bh + (size_t)n0*DD, Bl + (size_t)n0*DD };

    const int lr = tid >> 3, lkc = tid & 7;

#define G_ISSUE(ch, buf) do { \
    int k0_ = (ch) * 64; \
    _Pragma("unroll") \
    for (int t2 = 0; t2 < 4; t2++){ \
        uint32_t base_ = sb + (buf)*65536 + t2*16384; \
        _Pragma("unroll") \
        for (int i_ = 0; i_ < 4; i_++){ \
            int r_ = lr + i_*32; \
            cp16(base_ + SW128((uint32_t)(r_*128 + lkc*16)), \
                 srcs[t2] + (size_t)r_*DD + k0_ + lkc*8); \
        } \
    } \
    CP_COMMIT(); \
} while (0)

    G_ISSUE(0, 0);
    G_ISSUE(1, 1);

    float acc[16][4];
#pragma unroll
    for (int i = 0; i < 16; i++)
#pragma unroll
        for (int j = 0; j < 4; j++) acc[i][j] = 0.f;

    const int ar  = R0 + (lane & 15);
    const int akh = lane >> 4;
    const int bi  = lane & 7;
    const int grp = lane >> 3;

    for (int ch = 0; ch < 16; ch++){
        if (ch == 15) asm volatile("cp.async.wait_group 0;" ::: "memory");
        else          asm volatile("cp.async.wait_group 1;" ::: "memory");
        __syncthreads();
        uint32_t ba = sb + (ch & 1) * 65536;
#pragma unroll
        for (int k16 = 0; k16 < 4; k16++){
            uint32_t aoff = SW128((uint32_t)(ar*128 + (k16*2 + akh)*16));
            uint32_t ah[4], al[4];
            ldm4(ah, ba + aoff);
            ldm4(al, ba + 16384 + aoff);
#pragma unroll
            for (int np = 0; np < 8; np++){
                int bn  = np*16 + (grp >> 1)*8 + bi;
                int bkc = k16*2 + (grp & 1);
                uint32_t boff = SW128((uint32_t)(bn*128 + bkc*16));
                uint32_t bh[4], bl[4];
                ldm4(bh, ba + 2*16384 + boff);
                ldm4(bl, ba + 3*16384 + boff);
                mma_bf(acc[np*2],   ah, bh[0], bh[1]);
                mma_bf(acc[np*2+1], ah, bh[2], bh[3]);
                mma_bf(acc[np*2],   ah, bl[0], bl[1]);
                mma_bf(acc[np*2+1], ah, bl[2], bl[3]);
                mma_bf(acc[np*2],   al, bh[0], bh[1]);
                mma_bf(acc[np*2+1], al, bh[2], bh[3]);
            }
        }
        __syncthreads();
        if (ch + 2 < 16) G_ISSUE(ch + 2, ch & 1);
    }
#undef G_ISSUE

    // epilogue
    const int r1 = m0 + R0 + (lane >> 2), r2 = r1 + 8;
#pragma unroll
    for (int nf = 0; nf < 16; nf++){
        int c = n0 + nf*8 + (lane & 3)*2;
        float v0 = acc[nf][0], v1 = acc[nf][1], v2 = acc[nf][2], v3 = acc[nf][3];
        if (bias){
            float2 bb = *(const float2*)(bias + c);
            v0 += bb.x; v1 += bb.y; v2 += bb.x; v3 += bb.y;
        }
        if (mode == 0){
            v0 *= 0.125f; v1 *= 0.125f; v2 *= 0.125f; v3 *= 0.125f;
            int h = c >> 6, dh = c & 63;
#pragma unroll
            for (int rr = 0; rr < 2; rr++){
                int row = rr ? r2 : r1;
                float a = rr ? v2 : v0, b2 = rr ? v3 : v1;
                int b = row >> 10, q = row & 1023;
                size_t o = (((size_t)b*HH + h)*TQ + q)*64 + dh;
                __nv_bfloat16 ha, la, hb, lb;
                split2(a, ha, la); split2(b2, hb, lb);
                *(__nv_bfloat162*)(g_qh + o) = __halves2bfloat162(ha, hb);
                *(__nv_bfloat162*)(g_ql + o) = __halves2bfloat162(la, lb);
            }
        } else if (mode == 3){
            *(float2*)(outp + (size_t)r1*DD + c) = make_float2(v0, v1);
            *(float2*)(outp + (size_t)r2*DD + c) = make_float2(v2, v3);
        } else {
            float* dst = (mode == 1) ? kout : vout;
            int h = c >> 6, dh = c & 63;
#pragma unroll
            for (int rr = 0; rr < 2; rr++){
                int row = rr ? r2 : r1;
                float a = rr ? v2 : v0, b2 = rr ? v3 : v1;
                int b = row >> 10, q = row & 1023;
                size_t o = ((size_t)b*TKV + TQ + q)*DD + c;
                *(float2*)(dst + o) = make_float2(a, b2);
                if (mode == 1){
                    // fused K operand conversion (head-major hi/lo)
                    size_t ko = (((size_t)b*HH + h)*TKV + TQ + q)*64 + dh;
                    __nv_bfloat16 ha, la, hb, lb;
                    split2(a, ha, la); split2(b2, hb, lb);
                    *(__nv_bfloat162*)(g_kh + ko) = __halves2bfloat162(ha, hb);
                    *(__nv_bfloat162*)(g_kl + ko) = __halves2bfloat162(la, lb);
                }
            }
        }
    }
}

// ---------------- attention (HMMA, cp.async double-buffered K/V) ------------
#define A_QH 0
#define A_QL 16384
#define A_PH 32768
#define A_PL 65536
#define A_KV 98304                   // 2 stages x 65536: [KH,KL,VH,VL] x 16KB
#define A_SMEM (98304 + 131072)      // 229376 bytes

__global__ void __launch_bounds__(256, 1) attn_tc(const float* __restrict__ mask){
    extern __shared__ char sm[];
    uint32_t sb = smem_u32(sm);
    const int tid = threadIdx.x, wid = tid >> 5, lane = tid & 31;
    const int q0 = blockIdx.x * 128, h = blockIdx.y, b = blockIdx.z;
    const size_t bh = (size_t)b * HH + h;
    const int R0 = wid * 16;

    const __nv_bfloat16* Qbh = g_qh  + (bh*TQ + q0)*64;
    const __nv_bfloat16* Qbl = g_ql  + (bh*TQ + q0)*64;
    const __nv_bfloat16* Kbh = g_kh  + bh * (size_t)TKV * 64;
    const __nv_bfloat16* Kbl = g_kl  + bh * (size_t)TKV * 64;
    const __nv_bfloat16* Vbh = g_vth + bh * (size_t)64 * TKV;
    const __nv_bfloat16* Vbl = g_vtl + bh * (size_t)64 * TKV;

    // Q (persistent)
#pragma unroll
    for (int i = 0; i < 4; i++){
        int f = i*256 + tid, r = f >> 3, kc = f & 7;
        uint32_t d = SW128((uint32_t)(r*128 + kc*16));
        cp16(sb + A_QH + d, Qbh + f*8);
        cp16(sb + A_QL + d, Qbl + f*8);
    }
    CP_COMMIT();

#define A_ISSUE(it) do { \
    int kv0_ = (it) * 128; \
    uint32_t base_ = sb + A_KV + ((it) & 1) * 65536; \
    _Pragma("unroll") \
    for (int i_ = 0; i_ < 4; i_++){ \
        int f_ = i_*256 + tid; \
        int r_ = f_ >> 3, kc_ = f_ & 7; \
        uint32_t d_ = SW128((uint32_t)(r_*128 + kc_*16)); \
        cp16(base_ + d_,         Kbh + (size_t)kv0_*64 + f_*8); \
        cp16(base_ + 16384 + d_, Kbl + (size_t)kv0_*64 + f_*8); \
        int r2_ = f_ >> 4, kc2_ = f_ & 15; \
        uint32_t d2_ = (uint32_t)(r2_*256 + ((kc2_ >> 3) << 7) + (((kc2_ & 7) ^ (r2_ & 7)) << 4)); \
        cp16(base_ + 32768 + d2_, Vbh + (size_t)r2_*TKV + kv0_ + kc2_*8); \
        cp16(base_ + 49152 + d2_, Vbl + (size_t)r2_*TKV + kv0_ + kc2_*8); \
    } \
    CP_COMMIT(); \
} while (0)

    A_ISSUE(0);

    float Oacc[8][4];
#pragma unroll
    for (int i = 0; i < 8; i++)
#pragma unroll
        for (int j = 0; j < 4; j++) Oacc[i][j] = 0.f;
    float rs0 = 0.f, rs1 = 0.f;

    const int r1l = R0 + (lane >> 2), r2l = r1l + 8;
    const int ar  = R0 + (lane & 15);
    const int akh = lane >> 4;
    const int bi  = lane & 7;
    const int grp = lane >> 3;
    const float* m1 = mask + (size_t)(q0 + r1l)*TKV + (lane & 3)*2;
    const float* m2 = m1 + 8*TKV;

    for (int it = 0; it < 16; it++){
        int kv0 = it * 128;
        if (it < 15){
            A_ISSUE(it + 1);
            asm volatile("cp.async.wait_group 1;" ::: "memory");
        } else {
            asm volatile("cp.async.wait_group 0;" ::: "memory");
        }
        __syncthreads();
        uint32_t ba = sb + A_KV + (it & 1) * 65536;

        // S = Q K^T (128x128), 3-pass split
        float Sacc[16][4];
#pragma unroll
        for (int i = 0; i < 16; i++)
#pragma unroll
            for (int j = 0; j < 4; j++) Sacc[i][j] = 0.f;
#pragma unroll
        for (int k16 = 0; k16 < 4; k16++){
            uint32_t aoff = SW128((uint32_t)(ar*128 + (k16*2 + akh)*16));
            uint32_t qh[4], ql[4];
            ldm4(qh, sb + A_QH + aoff);
            ldm4(ql, sb + A_QL + aoff);
#pragma unroll
            for (int np = 0; np < 8; np++){
                int bn  = np*16 + (grp >> 1)*8 + bi;
                int bkc = k16*2 + (grp & 1);
                uint32_t boff = SW128((uint32_t)(bn*128 + bkc*16));
                uint32_t kh[4], kl[4];
                ldm4(kh, ba + boff);
                ldm4(kl, ba + 16384 + boff);
                mma_bf(Sacc[np*2],   qh, kh[0], kh[1]);
                mma_bf(Sacc[np*2+1], qh, kh[2], kh[3]);
                mma_bf(Sacc[np*2],   qh, kl[0], kl[1]);
                mma_bf(Sacc[np*2+1], qh, kl[2], kl[3]);
                mma_bf(Sacc[np*2],   ql, kh[0], kh[1]);
                mma_bf(Sacc[np*2+1], ql, kh[2], kh[3]);
            }
        }

        // P = exp(S + mask); row sums; store P hi/lo to smem
#pragma unroll
        for (int nf = 0; nf < 16; nf++){
            float2 ma = *(const float2*)(m1 + kv0 + nf*8);
            float2 mb = *(const float2*)(m2 + kv0 + nf*8);
            float p0 = __expf(Sacc[nf][0] + ma.x);
            float p1 = __expf(Sacc[nf][1] + ma.y);
            float p2 = __expf(Sacc[nf][2] + mb.x);
            float p3 = __expf(Sacc[nf][3] + mb.y);
            rs0 += p0 + p1; rs1 += p2 + p3;
            __nv_bfloat162 h01 = __floats2bfloat162_rn(p0, p1);
            __nv_bfloat162 l01 = __floats2bfloat162_rn(p0 - __low2float(h01), p1 - __high2float(h01));
            __nv_bfloat162 h23 = __floats2bfloat162_rn(p2, p3);
            __nv_bfloat162 l23 = __floats2bfloat162_rn(p2 - __low2float(h23), p3 - __high2float(h23));
            uint32_t o1 = (uint32_t)(r1l*256 + ((nf >> 3) << 7) + (((nf & 7) ^ (r1l & 7)) << 4) + (lane & 3)*4);
            uint32_t o2 = (uint32_t)(r2l*256 + ((nf >> 3) << 7) + (((nf & 7) ^ (r2l & 7)) << 4) + (lane & 3)*4);
            sts32(sb + A_PH + o1, bf2u(h01));
            sts32(sb + A_PL + o1, bf2u(l01));
            sts32(sb + A_PH + o2, bf2u(h23));
            sts32(sb + A_PL + o2, bf2u(l23));
        }
        __syncwarp();   // P rows are warp-private

        // O += P V^T (128x64 over k=128), 3-pass split
#pragma unroll
        for (int k16 = 0; k16 < 8; k16++){
            int pkc = k16*2 + akh;
            uint32_t poff = (uint32_t)(ar*256 + ((pkc >> 3) << 7) + (((pkc & 7) ^ (ar & 7)) << 4));
            uint32_t ph[4], pl[4];
            ldm4(ph, sb + A_PH + poff);
            ldm4(pl, sb + A_PL + poff);
#pragma unroll
            for (int np = 0; np < 4; np++){
                int vn  = np*16 + (grp >> 1)*8 + bi;
                int vkc = k16*2 + (grp & 1);
                uint32_t voff = (uint32_t)(vn*256 + ((vkc >> 3) << 7) + (((vkc & 7) ^ (vn & 7)) << 4));
                uint32_t vh[4], vl[4];
                ldm4(vh, ba + 32768 + voff);
                ldm4(vl, ba + 49152 + voff);
                mma_bf(Oacc[np*2],   ph, vh[0], vh[1]);
                mma_bf(Oacc[np*2+1], ph, vh[2], vh[3]);
                mma_bf(Oacc[np*2],   ph, vl[0], vl[1]);
                mma_bf(Oacc[np*2+1], ph, vl[2], vl[3]);
                mma_bf(Oacc[np*2],   pl, vh[0], vh[1]);
                mma_bf(Oacc[np*2+1], pl, vh[2], vh[3]);
            }
        }
        __syncthreads();   // buffer reuse guard
    }
#undef A_ISSUE

    // row-sum reduce across the 4 lanes sharing each row
    rs0 += __shfl_xor_sync(0xffffffffu, rs0, 1);
    rs0 += __shfl_xor_sync(0xffffffffu, rs0, 2);
    rs1 += __shfl_xor_sync(0xffffffffu, rs1, 1);
    rs1 += __shfl_xor_sync(0xffffffffu, rs1, 2);
    float inv0 = 1.f / rs0, inv1 = 1.f / rs1;

    // normalize + split + write attention output
    size_t base1 = ((size_t)(b*TQ + q0 + r1l))*DD + h*64;
    size_t base2 = ((size_t)(b*TQ + q0 + r2l))*DD + h*64;
#pragma unroll
    for (int nf = 0; nf < 8; nf++){
        int c = nf*8 + (lane & 3)*2;
        float v0 = Oacc[nf][0]*inv0, v1 = Oacc[nf][1]*inv0;
        float v2 = Oacc[nf][2]*inv1, v3 = Oacc[nf][3]*inv1;
        __nv_bfloat16 ha, la, hb, lb;
        split2(v0, ha, la); split2(v1, hb, lb);
        *(__nv_bfloat162*)(g_avh + base1 + c) = __halves2bfloat162(ha, hb);
        *(__nv_bfloat162*)(g_avl + base1 + c) = __halves2bfloat162(la, lb);
        split2(v2, ha, la); split2(v3, hb, lb);
        *(__nv_bfloat162*)(g_avh + base2 + c) = __halves2bfloat162(ha, hb);
        *(__nv_bfloat162*)(g_avl + base2 + c) = __halves2bfloat162(la, lb);
    }
}

// ---------------- launch ----------------------------------------------------
extern "C" void kernel_launch(void* const* d_in, const int* in_sizes, int n_in,
                              void* d_out, int out_size) {
    const float* x       = (const float*)d_in[0];
    const float* k_cache = (const float*)d_in[1];
    const float* v_cache = (const float*)d_in[2];
    const float* mask    = (const float*)d_in[3];
    const float* Wq      = (const float*)d_in[4];
    const float* bq      = (const float*)d_in[5];
    const float* Wk      = (const float*)d_in[6];
    const float* Wv      = (const float*)d_in[7];
    const float* bv      = (const float*)d_in[8];
    const float* Wo      = (const float*)d_in[9];
    const float* bo      = (const float*)d_in[10];

    float* outp = (float*)d_out;
    float* kout = outp + (size_t)BB * TQ * DD;
    float* vout = kout + (size_t)BB * TKV * DD;

    static int attr_done = 0;
    if (!attr_done){
        cudaFuncSetAttribute(gemm_tc, cudaFuncAttributeMaxDynamicSharedMemorySize, G_SMEM);
        cudaFuncSetAttribute(attn_tc, cudaFuncAttributeMaxDynamicSharedMemorySize, A_SMEM);
        attr_done = 1;
    }

    // 1) old cache rows -> output (+ K bf16 operands for old rows)
    {
        int n4 = BB * TQ * DD / 4;
        copy_old_cache<<<(n4 + 255)/256, 256>>>(
            (const float4*)k_cache, (const float4*)v_cache,
            (float4*)kout, (float4*)vout);
    }
    // 2) bf16 hi/lo conversions of x and weights
    conv_split<<<(BB*TQ*DD/4 + 255)/256, 256>>>((const float4*)x,  0, BB*TQ*DD/4);
    conv_split<<<(DD*DD/4 + 255)/256, 256>>>((const float4*)Wq, 1, DD*DD/4);
    conv_split<<<(DD*DD/4 + 255)/256, 256>>>((const float4*)Wk, 2, DD*DD/4);
    conv_split<<<(DD*DD/4 + 255)/256, 256>>>((const float4*)Wv, 3, DD*DD/4);
    conv_split<<<(DD*DD/4 + 255)/256, 256>>>((const float4*)Wo, 4, DD*DD/4);
    // 3) QKV projections (K operands fused in mode-1 epilogue)
    gemm_tc<<<dim3(DD/128, BB*TQ/128, 3), 256, G_SMEM>>>(0, bq, bv, bo, kout, vout, outp);
    // 4) V cache -> transposed bf16 hi/lo operands
    vconv<<<dim3(TKV/128, HH, BB), 256>>>(vout);
    // 5) attention
    attn_tc<<<dim3(TQ/128, HH, BB), 256, A_SMEM>>>(mask);
    // 6) output projection
    gemm_tc<<<dim3(DD/128, BB*TQ/128, 1), 256, G_SMEM>>>(3, bq, bv, bo, kout, vout, outp);
}

// round 8
// speedup vs baseline: 4.4360x; 1.0968x over previous
#include <cuda_runtime.h>
#include <cuda_bf16.h>
#include <cuda_fp16.h>
#include <cstdint>
#include <math.h>

#define BB 4
#define TQ 1024
#define TKV 2048
#define DD 1024
#define HH 16
#define DHD 64

// ---------------- device scratch (static; no allocations) -------------------
__device__ __nv_bfloat16 g_xh[BB*TQ*DD],  g_xl[BB*TQ*DD];
__device__ __nv_bfloat16 g_Wqh[DD*DD], g_Wql[DD*DD];
__device__ __nv_bfloat16 g_Wkh[DD*DD], g_Wkl[DD*DD];
__device__ __nv_bfloat16 g_Wvh[DD*DD], g_Wvl[DD*DD];
__device__ __nv_bfloat16 g_Woh[DD*DD], g_Wol[DD*DD];
__device__ __half        g_qhf[BB*TQ*DD];                    // [b,h,tq,64], x0.125, fp16
__device__ __half        g_khf[BB*TKV*DD];                   // [b,h,kv,64], fp16
__device__ __nv_bfloat16 g_vth[BB*TKV*DD], g_vtl[BB*TKV*DD]; // [b,h,64,kv]
__device__ __nv_bfloat16 g_avh[BB*TQ*DD], g_avl[BB*TQ*DD];   // attn out [m,1024]

// ---------------- helpers ---------------------------------------------------
__device__ __forceinline__ uint32_t smem_u32(const void* p){
    uint32_t a;
    asm("{ .reg .u64 t; cvta.to.shared.u64 t, %1; cvt.u32.u64 %0, t; }" : "=r"(a) : "l"(p));
    return a;
}
#define SW128(o) ((o) ^ (((o) >> 3) & 0x70))

__device__ __forceinline__ void ldm4(uint32_t* r, uint32_t addr){
    asm volatile("ldmatrix.sync.aligned.m8n8.x4.shared.b16 {%0,%1,%2,%3}, [%4];"
        : "=r"(r[0]), "=r"(r[1]), "=r"(r[2]), "=r"(r[3]) : "r"(addr));
}
__device__ __forceinline__ void mma_bf(float* c, const uint32_t* a, uint32_t b0, uint32_t b1){
    asm volatile("mma.sync.aligned.m16n8k16.row.col.f32.bf16.bf16.f32 "
        "{%0,%1,%2,%3}, {%4,%5,%6,%7}, {%8,%9}, {%0,%1,%2,%3};"
        : "+f"(c[0]), "+f"(c[1]), "+f"(c[2]), "+f"(c[3])
        : "r"(a[0]), "r"(a[1]), "r"(a[2]), "r"(a[3]), "r"(b0), "r"(b1));
}
__device__ __forceinline__ void mma_f16(float* c, const uint32_t* a, uint32_t b0, uint32_t b1){
    asm volatile("mma.sync.aligned.m16n8k16.row.col.f32.f16.f16.f32 "
        "{%0,%1,%2,%3}, {%4,%5,%6,%7}, {%8,%9}, {%0,%1,%2,%3};"
        : "+f"(c[0]), "+f"(c[1]), "+f"(c[2]), "+f"(c[3])
        : "r"(a[0]), "r"(a[1]), "r"(a[2]), "r"(a[3]), "r"(b0), "r"(b1));
}
__device__ __forceinline__ void cp16(uint32_t dst, const void* src){
    asm volatile("cp.async.cg.shared.global [%0], [%1], 16;" :: "r"(dst), "l"(src));
}
#define CP_COMMIT() asm volatile("cp.async.commit_group;")
__device__ __forceinline__ void sts128(uint32_t addr, uint4 v){
    asm volatile("st.shared.v4.b32 [%0], {%1,%2,%3,%4};"
        :: "r"(addr), "r"(v.x), "r"(v.y), "r"(v.z), "r"(v.w));
}
__device__ __forceinline__ void sts32(uint32_t addr, uint32_t v){
    asm volatile("st.shared.b32 [%0], %1;" :: "r"(addr), "r"(v));
}
__device__ __forceinline__ void split2(float x, __nv_bfloat16& h, __nv_bfloat16& l){
    h = __float2bfloat16(x);
    l = __float2bfloat16(x - __bfloat162float(h));
}
__device__ __forceinline__ uint32_t bf2u(__nv_bfloat162 v){
    return *reinterpret_cast<uint32_t*>(&v);
}

// ---------------- small prep kernels ---------------------------------------
// old cache rows -> output caches; ALSO emit K fp16 head-major operands
__global__ void copy_old_cache(const float4* __restrict__ ksrc,
                               const float4* __restrict__ vsrc,
                               float4* __restrict__ kdst,
                               float4* __restrict__ vdst){
    int i = blockIdx.x * blockDim.x + threadIdx.x;
    const int per_b = TQ * DD / 4;
    if (i >= BB * per_b) return;
    int b = i / per_b;
    int rem = i - b * per_b;
    size_t idx = (size_t)b * (TKV * DD / 4) + rem;
    float4 kv4 = ksrc[idx];
    kdst[idx] = kv4;
    vdst[idx] = vsrc[idx];
    int t = rem >> 8;
    int d = (rem & 255) * 4;
    int h = d >> 6, dh = d & 63;
    size_t o = (((size_t)b*HH + h)*TKV + t)*64 + dh;
    *(__half2*)(g_khf + o)     = __floats2half2_rn(kv4.x, kv4.y);
    *(__half2*)(g_khf + o + 2) = __floats2half2_rn(kv4.z, kv4.w);
}

__global__ void conv_split(const float4* __restrict__ src, int which, int n4){
    int i = blockIdx.x * blockDim.x + threadIdx.x;
    if (i >= n4) return;
    __nv_bfloat16 *H, *L;
    switch (which){
        case 0: H = g_xh;  L = g_xl;  break;
        case 1: H = g_Wqh; L = g_Wql; break;
        case 2: H = g_Wkh; L = g_Wkl; break;
        case 3: H = g_Wvh; L = g_Wvl; break;
        default:H = g_Woh; L = g_Wol; break;
    }
    float4 v = src[i];
    float vs[4] = {v.x, v.y, v.z, v.w};
    __nv_bfloat16 hh[4], ll[4];
#pragma unroll
    for (int j = 0; j < 4; j++) split2(vs[j], hh[j], ll[j]);
    ((__nv_bfloat162*)H)[i*2+0] = __halves2bfloat162(hh[0], hh[1]);
    ((__nv_bfloat162*)H)[i*2+1] = __halves2bfloat162(hh[2], hh[3]);
    ((__nv_bfloat162*)L)[i*2+0] = __halves2bfloat162(ll[0], ll[1]);
    ((__nv_bfloat162*)L)[i*2+1] = __halves2bfloat162(ll[2], ll[3]);
}

// V cache [b,kv,D] fp32 -> transposed bf16 hi/lo [b,h,64,kv]
__global__ void vconv(const float* __restrict__ vc){
    __shared__ float t[128][65];
    int kv0 = blockIdx.x * 128, h = blockIdx.y, b = blockIdx.z;
    int tid = threadIdx.x;
    for (int i = tid; i < 128*16; i += 256){
        int r = i >> 4, c4 = i & 15;
        float4 v = *(const float4*)(vc + ((size_t)(b*TKV + kv0 + r))*DD + h*64 + c4*4);
        t[r][c4*4+0] = v.x; t[r][c4*4+1] = v.y; t[r][c4*4+2] = v.z; t[r][c4*4+3] = v.w;
    }
    __syncthreads();
    for (int i = tid; i < 64*128; i += 256){
        int dh = i >> 7, j = i & 127;
        float v = t[j][dh];
        __nv_bfloat16 hh, ll; split2(v, hh, ll);
        size_t o = (((size_t)b*HH + h)*64 + dh)*TKV + kv0 + j;
        g_vth[o] = hh; g_vtl[o] = ll;
    }
}

// ---------------- tensor-core (HMMA) projection GEMM -----------------------
#define G_SMEM 131072

__global__ void __launch_bounds__(256, 1) gemm_tc(int mode_base,
    const float* __restrict__ bq, const float* __restrict__ bvv, const float* __restrict__ bo,
    float* __restrict__ kout, float* __restrict__ vout, float* __restrict__ outp){
    extern __shared__ char sm[];
    const int mode = mode_base + blockIdx.z;
    const __nv_bfloat16 *Ah, *Al, *Bh, *Bl;
    const float* bias;
    if (mode == 0)      { Ah=g_xh;  Al=g_xl;  Bh=g_Wqh; Bl=g_Wql; bias=bq;  }
    else if (mode == 1) { Ah=g_xh;  Al=g_xl;  Bh=g_Wkh; Bl=g_Wkl; bias=0;   }
    else if (mode == 2) { Ah=g_xh;  Al=g_xl;  Bh=g_Wvh; Bl=g_Wvl; bias=bvv; }
    else                { Ah=g_avh; Al=g_avl; Bh=g_Woh; Bl=g_Wol; bias=bo;  }

    uint32_t sb = smem_u32(sm);
    const int tid = threadIdx.x, wid = tid >> 5, lane = tid & 31;
    const int m0 = blockIdx.y * 128, n0 = blockIdx.x * 128;
    const int R0 = wid * 16;

    const __nv_bfloat16* srcs[4] = {
        Ah + (size_t)m0*DD, Al + (size_t)m0*DD,
        Bh + (size_t)n0*DD, Bl + (size_t)n0*DD };

    const int lr = tid >> 3, lkc = tid & 7;

#define G_ISSUE(ch, buf) do { \
    int k0_ = (ch) * 64; \
    _Pragma("unroll") \
    for (int t2 = 0; t2 < 4; t2++){ \
        uint32_t base_ = sb + (buf)*65536 + t2*16384; \
        _Pragma("unroll") \
        for (int i_ = 0; i_ < 4; i_++){ \
            int r_ = lr + i_*32; \
            cp16(base_ + SW128((uint32_t)(r_*128 + lkc*16)), \
                 srcs[t2] + (size_t)r_*DD + k0_ + lkc*8); \
        } \
    } \
    CP_COMMIT(); \
} while (0)

    G_ISSUE(0, 0);
    G_ISSUE(1, 1);

    float acc[16][4];
#pragma unroll
    for (int i = 0; i < 16; i++)
#pragma unroll
        for (int j = 0; j < 4; j++) acc[i][j] = 0.f;

    const int ar  = R0 + (lane & 15);
    const int akh = lane >> 4;
    const int bi  = lane & 7;
    const int grp = lane >> 3;

    for (int ch = 0; ch < 16; ch++){
        if (ch == 15) asm volatile("cp.async.wait_group 0;" ::: "memory");
        else          asm volatile("cp.async.wait_group 1;" ::: "memory");
        __syncthreads();
        uint32_t ba = sb + (ch & 1) * 65536;
#pragma unroll
        for (int k16 = 0; k16 < 4; k16++){
            uint32_t aoff = SW128((uint32_t)(ar*128 + (k16*2 + akh)*16));
            uint32_t ah[4], al[4];
            ldm4(ah, ba + aoff);
            ldm4(al, ba + 16384 + aoff);
#pragma unroll
            for (int np = 0; np < 8; np++){
                int bn  = np*16 + (grp >> 1)*8 + bi;
                int bkc = k16*2 + (grp & 1);
                uint32_t boff = SW128((uint32_t)(bn*128 + bkc*16));
                uint32_t bh[4], bl[4];
                ldm4(bh, ba + 2*16384 + boff);
                ldm4(bl, ba + 3*16384 + boff);
                mma_bf(acc[np*2],   ah, bh[0], bh[1]);
                mma_bf(acc[np*2+1], ah, bh[2], bh[3]);
                mma_bf(acc[np*2],   ah, bl[0], bl[1]);
                mma_bf(acc[np*2+1], ah, bl[2], bl[3]);
                mma_bf(acc[np*2],   al, bh[0], bh[1]);
                mma_bf(acc[np*2+1], al, bh[2], bh[3]);
            }
        }
        __syncthreads();
        if (ch + 2 < 16) G_ISSUE(ch + 2, ch & 1);
    }
#undef G_ISSUE

    // epilogue
    const int r1 = m0 + R0 + (lane >> 2), r2 = r1 + 8;
#pragma unroll
    for (int nf = 0; nf < 16; nf++){
        int c = n0 + nf*8 + (lane & 3)*2;
        float v0 = acc[nf][0], v1 = acc[nf][1], v2 = acc[nf][2], v3 = acc[nf][3];
        if (bias){
            float2 bb = *(const float2*)(bias + c);
            v0 += bb.x; v1 += bb.y; v2 += bb.x; v3 += bb.y;
        }
        if (mode == 0){
            v0 *= 0.125f; v1 *= 0.125f; v2 *= 0.125f; v3 *= 0.125f;
            int h = c >> 6, dh = c & 63;
#pragma unroll
            for (int rr = 0; rr < 2; rr++){
                int row = rr ? r2 : r1;
                float a = rr ? v2 : v0, b2 = rr ? v3 : v1;
                int b = row >> 10, q = row & 1023;
                size_t o = (((size_t)b*HH + h)*TQ + q)*64 + dh;
                *(__half2*)(g_qhf + o) = __floats2half2_rn(a, b2);
            }
        } else if (mode == 3){
            *(float2*)(outp + (size_t)r1*DD + c) = make_float2(v0, v1);
            *(float2*)(outp + (size_t)r2*DD + c) = make_float2(v2, v3);
        } else {
            float* dst = (mode == 1) ? kout : vout;
            int h = c >> 6, dh = c & 63;
#pragma unroll
            for (int rr = 0; rr < 2; rr++){
                int row = rr ? r2 : r1;
                float a = rr ? v2 : v0, b2 = rr ? v3 : v1;
                int b = row >> 10, q = row & 1023;
                size_t o = ((size_t)b*TKV + TQ + q)*DD + c;
                *(float2*)(dst + o) = make_float2(a, b2);
                if (mode == 1){
                    size_t ko = (((size_t)b*HH + h)*TKV + TQ + q)*64 + dh;
                    *(__half2*)(g_khf + ko) = __floats2half2_rn(a, b2);
                }
            }
        }
    }
}

// ---------------- attention (fp16 1-pass S, bf16 3-pass PV) -----------------
// smem: Q 16K | PH 32K | PL 32K | 3 stages x 48K {K fp16, VH, VL}
#define A_QH 0
#define A_PH 16384
#define A_PL 49152
#define A_ST 81920
#define A_STAGE 49152
#define A_SMEM (81920 + 3*49152)     // 229376 (224KB)

__global__ void __launch_bounds__(256, 1) attn_tc(const float* __restrict__ mask){
    extern __shared__ char sm[];
    uint32_t sb = smem_u32(sm);
    const int tid = threadIdx.x, wid = tid >> 5, lane = tid & 31;
    const int q0 = blockIdx.x * 128, h = blockIdx.y, b = blockIdx.z;
    const size_t bh = (size_t)b * HH + h;
    const int R0 = wid * 16;

    const __half* Qf = g_qhf + (bh*TQ + q0)*64;
    const __half* Kf = g_khf + bh * (size_t)TKV * 64;
    const __nv_bfloat16* Vbh = g_vth + bh * (size_t)64 * TKV;
    const __nv_bfloat16* Vbl = g_vtl + bh * (size_t)64 * TKV;

    // Q (persistent, fp16)
#pragma unroll
    for (int i = 0; i < 4; i++){
        int f = i*256 + tid, r = f >> 3, kc = f & 7;
        cp16(sb + A_QH + SW128((uint32_t)(r*128 + kc*16)), Qf + f*8);
    }
    CP_COMMIT();

#define A_ISSUE(it) do { \
    int kv0_ = (it) * 128; \
    uint32_t base_ = sb + A_ST + ((it) % 3) * A_STAGE; \
    _Pragma("unroll") \
    for (int i_ = 0; i_ < 4; i_++){ \
        int f_ = i_*256 + tid; \
        int r_ = f_ >> 3, kc_ = f_ & 7; \
        cp16(base_ + SW128((uint32_t)(r_*128 + kc_*16)), Kf + (size_t)kv0_*64 + f_*8); \
        int r2_ = f_ >> 4, kc2_ = f_ & 15; \
        uint32_t d2_ = (uint32_t)(r2_*256 + ((kc2_ >> 3) << 7) + (((kc2_ & 7) ^ (r2_ & 7)) << 4)); \
        cp16(base_ + 16384 + d2_, Vbh + (size_t)r2_*TKV + kv0_ + kc2_*8); \
        cp16(base_ + 32768 + d2_, Vbl + (size_t)r2_*TKV + kv0_ + kc2_*8); \
    } \
    CP_COMMIT(); \
} while (0)

    A_ISSUE(0);
    A_ISSUE(1);

    float Oacc[8][4];
#pragma unroll
    for (int i = 0; i < 8; i++)
#pragma unroll
        for (int j = 0; j < 4; j++) Oacc[i][j] = 0.f;
    float rs0 = 0.f, rs1 = 0.f;

    const int r1l = R0 + (lane >> 2), r2l = r1l + 8;
    const int ar  = R0 + (lane & 15);
    const int akh = lane >> 4;
    const int bi  = lane & 7;
    const int grp = lane >> 3;
    const float* m1 = mask + (size_t)(q0 + r1l)*TKV + (lane & 3)*2;
    const float* m2 = m1 + 8*TKV;

    for (int it = 0; it < 16; it++){
        int kv0 = it * 128;
        if (it < 15) asm volatile("cp.async.wait_group 1;" ::: "memory");
        else         asm volatile("cp.async.wait_group 0;" ::: "memory");
        __syncthreads();
        uint32_t ba = sb + A_ST + (it % 3) * A_STAGE;

        // S = Q K^T (128x128), 1-pass fp16
        float Sacc[16][4];
#pragma unroll
        for (int i = 0; i < 16; i++)
#pragma unroll
            for (int j = 0; j < 4; j++) Sacc[i][j] = 0.f;
#pragma unroll
        for (int k16 = 0; k16 < 4; k16++){
            uint32_t aoff = SW128((uint32_t)(ar*128 + (k16*2 + akh)*16));
            uint32_t qh[4];
            ldm4(qh, sb + A_QH + aoff);
#pragma unroll
            for (int np = 0; np < 8; np++){
                int bn  = np*16 + (grp >> 1)*8 + bi;
                int bkc = k16*2 + (grp & 1);
                uint32_t boff = SW128((uint32_t)(bn*128 + bkc*16));
                uint32_t kh[4];
                ldm4(kh, ba + boff);
                mma_f16(Sacc[np*2],   qh, kh[0], kh[1]);
                mma_f16(Sacc[np*2+1], qh, kh[2], kh[3]);
            }
        }

        // P = exp(S + mask); row sums; store P hi/lo (bf16) to smem
#pragma unroll
        for (int nf = 0; nf < 16; nf++){
            float2 ma = *(const float2*)(m1 + kv0 + nf*8);
            float2 mb = *(const float2*)(m2 + kv0 + nf*8);
            float p0 = __expf(Sacc[nf][0] + ma.x);
            float p1 = __expf(Sacc[nf][1] + ma.y);
            float p2 = __expf(Sacc[nf][2] + mb.x);
            float p3 = __expf(Sacc[nf][3] + mb.y);
            rs0 += p0 + p1; rs1 += p2 + p3;
            __nv_bfloat162 h01 = __floats2bfloat162_rn(p0, p1);
            __nv_bfloat162 l01 = __floats2bfloat162_rn(p0 - __low2float(h01), p1 - __high2float(h01));
            __nv_bfloat162 h23 = __floats2bfloat162_rn(p2, p3);
            __nv_bfloat162 l23 = __floats2bfloat162_rn(p2 - __low2float(h23), p3 - __high2float(h23));
            uint32_t o1 = (uint32_t)(r1l*256 + ((nf >> 3) << 7) + (((nf & 7) ^ (r1l & 7)) << 4) + (lane & 3)*4);
            uint32_t o2 = (uint32_t)(r2l*256 + ((nf >> 3) << 7) + (((nf & 7) ^ (r2l & 7)) << 4) + (lane & 3)*4);
            sts32(sb + A_PH + o1, bf2u(h01));
            sts32(sb + A_PL + o1, bf2u(l01));
            sts32(sb + A_PH + o2, bf2u(h23));
            sts32(sb + A_PL + o2, bf2u(l23));
        }
        __syncwarp();   // P rows are warp-private

        // O += P V^T (128x64 over k=128), 3-pass bf16 split
#pragma unroll
        for (int k16 = 0; k16 < 8; k16++){
            int pkc = k16*2 + akh;
            uint32_t poff = (uint32_t)(ar*256 + ((pkc >> 3) << 7) + (((pkc & 7) ^ (ar & 7)) << 4));
            uint32_t ph[4], pl[4];
            ldm4(ph, sb + A_PH + poff);
            ldm4(pl, sb + A_PL + poff);
#pragma unroll
            for (int np = 0; np < 4; np++){
                int vn  = np*16 + (grp >> 1)*8 + bi;
                int vkc = k16*2 + (grp & 1);
                uint32_t voff = (uint32_t)(vn*256 + ((vkc >> 3) << 7) + (((vkc & 7) ^ (vn & 7)) << 4));
                uint32_t vh[4], vl[4];
                ldm4(vh, ba + 16384 + voff);
                ldm4(vl, ba + 32768 + voff);
                mma_bf(Oacc[np*2],   ph, vh[0], vh[1]);
                mma_bf(Oacc[np*2+1], ph, vh[2], vh[3]);
                mma_bf(Oacc[np*2],   ph, vl[0], vl[1]);
                mma_bf(Oacc[np*2+1], ph, vl[2], vl[3]);
                mma_bf(Oacc[np*2],   pl, vh[0], vh[1]);
                mma_bf(Oacc[np*2+1], pl, vh[2], vh[3]);
            }
        }

        // prefetch stage it+2 (buffer (it+2)%3 was last read in iter it-1;
        // all warps passed this iter's barrier, so it is free)
        if (it < 14) A_ISSUE(it + 2);
    }
#undef A_ISSUE

    // row-sum reduce across the 4 lanes sharing each row
    rs0 += __shfl_xor_sync(0xffffffffu, rs0, 1);
    rs0 += __shfl_xor_sync(0xffffffffu, rs0, 2);
    rs1 += __shfl_xor_sync(0xffffffffu, rs1, 1);
    rs1 += __shfl_xor_sync(0xffffffffu, rs1, 2);
    float inv0 = 1.f / rs0, inv1 = 1.f / rs1;

    // normalize + split + write attention output
    size_t base1 = ((size_t)(b*TQ + q0 + r1l))*DD + h*64;
    size_t base2 = ((size_t)(b*TQ + q0 + r2l))*DD + h*64;
#pragma unroll
    for (int nf = 0; nf < 8; nf++){
        int c = nf*8 + (lane & 3)*2;
        float v0 = Oacc[nf][0]*inv0, v1 = Oacc[nf][1]*inv0;
        float v2 = Oacc[nf][2]*inv1, v3 = Oacc[nf][3]*inv1;
        __nv_bfloat16 ha, la, hb, lb;
        split2(v0, ha, la); split2(v1, hb, lb);
        *(__nv_bfloat162*)(g_avh + base1 + c) = __halves2bfloat162(ha, hb);
        *(__nv_bfloat162*)(g_avl + base1 + c) = __halves2bfloat162(la, lb);
        split2(v2, ha, la); split2(v3, hb, lb);
        *(__nv_bfloat162*)(g_avh + base2 + c) = __halves2bfloat162(ha, hb);
        *(__nv_bfloat162*)(g_avl + base2 + c) = __halves2bfloat162(la, lb);
    }
}

// ---------------- launch ----------------------------------------------------
extern "C" void kernel_launch(void* const* d_in, const int* in_sizes, int n_in,
                              void* d_out, int out_size) {
    const float* x       = (const float*)d_in[0];
    const float* k_cache = (const float*)d_in[1];
    const float* v_cache = (const float*)d_in[2];
    const float* mask    = (const float*)d_in[3];
    const float* Wq      = (const float*)d_in[4];
    const float* bq      = (const float*)d_in[5];
    const float* Wk      = (const float*)d_in[6];
    const float* Wv      = (const float*)d_in[7];
    const float* bv      = (const float*)d_in[8];
    const float* Wo      = (const float*)d_in[9];
    const float* bo      = (const float*)d_in[10];

    float* outp = (float*)d_out;
    float* kout = outp + (size_t)BB * TQ * DD;
    float* vout = kout + (size_t)BB * TKV * DD;

    static int attr_done = 0;
    if (!attr_done){
        cudaFuncSetAttribute(gemm_tc, cudaFuncAttributeMaxDynamicSharedMemorySize, G_SMEM);
        cudaFuncSetAttribute(attn_tc, cudaFuncAttributeMaxDynamicSharedMemorySize, A_SMEM);
        attr_done = 1;
    }

    // 1) old cache rows -> output (+ K fp16 operands for old rows)
    {
        int n4 = BB * TQ * DD / 4;
        copy_old_cache<<<(n4 + 255)/256, 256>>>(
            (const float4*)k_cache, (const float4*)v_cache,
            (float4*)kout, (float4*)vout);
    }
    // 2) bf16 hi/lo conversions of x and weights
    conv_split<<<(BB*TQ*DD/4 + 255)/256, 256>>>((const float4*)x,  0, BB*TQ*DD/4);
    conv_split<<<(DD*DD/4 + 255)/256, 256>>>((const float4*)Wq, 1, DD*DD/4);
    conv_split<<<(DD*DD/4 + 255)/256, 256>>>((const float4*)Wk, 2, DD*DD/4);
    conv_split<<<(DD*DD/4 + 255)/256, 256>>>((const float4*)Wv, 3, DD*DD/4);
    conv_split<<<(DD*DD/4 + 255)/256, 256>>>((const float4*)Wo, 4, DD*DD/4);
    // 3) QKV projections (K fp16 operands fused in mode-1 epilogue)
    gemm_tc<<<dim3(DD/128, BB*TQ/128, 3), 256, G_SMEM>>>(0, bq, bv, bo, kout, vout, outp);
    // 4) V cache -> transposed bf16 hi/lo operands
    vconv<<<dim3(TKV/128, HH, BB), 256>>>(vout);
    // 5) attention
    attn_tc<<<dim3(TQ/128, HH, BB), 256, A_SMEM>>>(mask);
    // 6) output projection
    gemm_tc<<<dim3(DD/128, BB*TQ/128, 1), 256, G_SMEM>>>(3, bq, bv, bo, kout, vout, outp);
}

// round 9
// speedup vs baseline: 5.5430x; 1.2496x over previous
#include <cuda_runtime.h>
#include <cuda_bf16.h>
#include <cuda_fp16.h>
#include <cstdint>
#include <math.h>

#define BB 4
#define TQ 1024
#define TKV 2048
#define DD 1024
#define HH 16
#define DHD 64

// ---------------- device scratch (static; no allocations) -------------------
__device__ __half g_xh[BB*TQ*DD],  g_xl[BB*TQ*DD];   // x fp16 hi/lo
__device__ __half g_Wq[DD*DD], g_Wk[DD*DD], g_Wv[DD*DD], g_Wo[DD*DD]; // single fp16
__device__ __half g_qhf[BB*TQ*DD];                   // [b,h,tq,64], x0.125
__device__ __half g_khf[BB*TKV*DD];                  // [b,h,kv,64]
__device__ __half g_vt[BB*TKV*DD];                   // [b,h,64,kv] transposed
__device__ __half g_avh[BB*TQ*DD], g_avl[BB*TQ*DD];  // attn out fp16 hi/lo [m,1024]

// ---------------- helpers ---------------------------------------------------
__device__ __forceinline__ uint32_t smem_u32(const void* p){
    uint32_t a;
    asm("{ .reg .u64 t; cvta.to.shared.u64 t, %1; cvt.u32.u64 %0, t; }" : "=r"(a) : "l"(p));
    return a;
}
#define SW128(o) ((o) ^ (((o) >> 3) & 0x70))

__device__ __forceinline__ void ldm4(uint32_t* r, uint32_t addr){
    asm volatile("ldmatrix.sync.aligned.m8n8.x4.shared.b16 {%0,%1,%2,%3}, [%4];"
        : "=r"(r[0]), "=r"(r[1]), "=r"(r[2]), "=r"(r[3]) : "r"(addr));
}
__device__ __forceinline__ void mma_f16(float* c, const uint32_t* a, uint32_t b0, uint32_t b1){
    asm volatile("mma.sync.aligned.m16n8k16.row.col.f32.f16.f16.f32 "
        "{%0,%1,%2,%3}, {%4,%5,%6,%7}, {%8,%9}, {%0,%1,%2,%3};"
        : "+f"(c[0]), "+f"(c[1]), "+f"(c[2]), "+f"(c[3])
        : "r"(a[0]), "r"(a[1]), "r"(a[2]), "r"(a[3]), "r"(b0), "r"(b1));
}
__device__ __forceinline__ void cp16(uint32_t dst, const void* src){
    asm volatile("cp.async.cg.shared.global [%0], [%1], 16;" :: "r"(dst), "l"(src));
}
#define CP_COMMIT() asm volatile("cp.async.commit_group;")
__device__ __forceinline__ void sts32(uint32_t addr, uint32_t v){
    asm volatile("st.shared.b32 [%0], %1;" :: "r"(addr), "r"(v));
}
__device__ __forceinline__ void split2h(float x, __half& h, __half& l){
    h = __float2half_rn(x);
    l = __float2half_rn(x - __half2float(h));
}
__device__ __forceinline__ uint32_t h2u(__half2 v){
    return *reinterpret_cast<uint32_t*>(&v);
}

// ---------------- small prep kernels ---------------------------------------
// old cache rows -> output caches; ALSO emit K fp16 head-major operands
__global__ void copy_old_cache(const float4* __restrict__ ksrc,
                               const float4* __restrict__ vsrc,
                               float4* __restrict__ kdst,
                               float4* __restrict__ vdst){
    int i = blockIdx.x * blockDim.x + threadIdx.x;
    const int per_b = TQ * DD / 4;
    if (i >= BB * per_b) return;
    int b = i / per_b;
    int rem = i - b * per_b;
    size_t idx = (size_t)b * (TKV * DD / 4) + rem;
    float4 kv4 = ksrc[idx];
    kdst[idx] = kv4;
    vdst[idx] = vsrc[idx];
    int t = rem >> 8;
    int d = (rem & 255) * 4;
    int h = d >> 6, dh = d & 63;
    size_t o = (((size_t)b*HH + h)*TKV + t)*64 + dh;
    *(__half2*)(g_khf + o)     = __floats2half2_rn(kv4.x, kv4.y);
    *(__half2*)(g_khf + o + 2) = __floats2half2_rn(kv4.z, kv4.w);
}

// x fp32 -> fp16 hi/lo
__global__ void conv_x(const float4* __restrict__ src, int n4){
    int i = blockIdx.x * blockDim.x + threadIdx.x;
    if (i >= n4) return;
    float4 v = src[i];
    float vs[4] = {v.x, v.y, v.z, v.w};
    __half hh[4], ll[4];
#pragma unroll
    for (int j = 0; j < 4; j++) split2h(vs[j], hh[j], ll[j]);
    ((__half2*)g_xh)[i*2+0] = __halves2half2(hh[0], hh[1]);
    ((__half2*)g_xh)[i*2+1] = __halves2half2(hh[2], hh[3]);
    ((__half2*)g_xl)[i*2+0] = __halves2half2(ll[0], ll[1]);
    ((__half2*)g_xl)[i*2+1] = __halves2half2(ll[2], ll[3]);
}

// weight fp32 -> single fp16
__global__ void conv_w(const float4* __restrict__ src, int which, int n4){
    int i = blockIdx.x * blockDim.x + threadIdx.x;
    if (i >= n4) return;
    __half* W;
    switch (which){
        case 0: W = g_Wq; break;
        case 1: W = g_Wk; break;
        case 2: W = g_Wv; break;
        default:W = g_Wo; break;
    }
    float4 v = src[i];
    ((__half2*)W)[i*2+0] = __floats2half2_rn(v.x, v.y);
    ((__half2*)W)[i*2+1] = __floats2half2_rn(v.z, v.w);
}

// V cache [b,kv,D] fp32 -> transposed single fp16 [b,h,64,kv]
__global__ void vconv(const float* __restrict__ vc){
    __shared__ float t[128][65];
    int kv0 = blockIdx.x * 128, h = blockIdx.y, b = blockIdx.z;
    int tid = threadIdx.x;
    for (int i = tid; i < 128*16; i += 256){
        int r = i >> 4, c4 = i & 15;
        float4 v = *(const float4*)(vc + ((size_t)(b*TKV + kv0 + r))*DD + h*64 + c4*4);
        t[r][c4*4+0] = v.x; t[r][c4*4+1] = v.y; t[r][c4*4+2] = v.z; t[r][c4*4+3] = v.w;
    }
    __syncthreads();
    for (int i = tid; i < 64*128; i += 256){
        int dh = i >> 7, j = i & 127;
        size_t o = (((size_t)b*HH + h)*64 + dh)*TKV + kv0 + j;
        g_vt[o] = __float2half_rn(t[j][dh]);
    }
}

// ---------------- fp16 2-pass projection GEMM -------------------------------
// C[m,n] = sum_k A[m,k]*W[n,k] (+bias). 128x128 block, BK=64, double buffer.
// smem: 2 stages x {Ah 16K, Al 16K, W 16K} = 98304
#define G_STAGE 49152
#define G_SMEM  98304

__global__ void __launch_bounds__(256, 1) gemm_tc(int mode_base,
    const float* __restrict__ bq, const float* __restrict__ bvv, const float* __restrict__ bo,
    float* __restrict__ kout, float* __restrict__ vout, float* __restrict__ outp){
    extern __shared__ char sm[];
    const int mode = mode_base + blockIdx.z;
    const __half *Ah, *Al, *W;
    const float* bias;
    if (mode == 0)      { Ah=g_xh;  Al=g_xl;  W=g_Wq; bias=bq;  }
    else if (mode == 1) { Ah=g_xh;  Al=g_xl;  W=g_Wk; bias=0;   }
    else if (mode == 2) { Ah=g_xh;  Al=g_xl;  W=g_Wv; bias=bvv; }
    else                { Ah=g_avh; Al=g_avl; W=g_Wo; bias=bo;  }

    uint32_t sb = smem_u32(sm);
    const int tid = threadIdx.x, wid = tid >> 5, lane = tid & 31;
    const int m0 = blockIdx.y * 128, n0 = blockIdx.x * 128;
    const int R0 = wid * 16;

    const __half* srcs[3] = { Ah + (size_t)m0*DD, Al + (size_t)m0*DD, W + (size_t)n0*DD };
    const int lr = tid >> 3, lkc = tid & 7;

#define G_ISSUE(ch, buf) do { \
    int k0_ = (ch) * 64; \
    _Pragma("unroll") \
    for (int t2 = 0; t2 < 3; t2++){ \
        uint32_t base_ = sb + (buf)*G_STAGE + t2*16384; \
        _Pragma("unroll") \
        for (int i_ = 0; i_ < 4; i_++){ \
            int r_ = lr + i_*32; \
            cp16(base_ + SW128((uint32_t)(r_*128 + lkc*16)), \
                 srcs[t2] + (size_t)r_*DD + k0_ + lkc*8); \
        } \
    } \
    CP_COMMIT(); \
} while (0)

    G_ISSUE(0, 0);
    G_ISSUE(1, 1);

    float acc[16][4];
#pragma unroll
    for (int i = 0; i < 16; i++)
#pragma unroll
        for (int j = 0; j < 4; j++) acc[i][j] = 0.f;

    const int ar  = R0 + (lane & 15);
    const int akh = lane >> 4;
    const int bi  = lane & 7;
    const int grp = lane >> 3;

    for (int ch = 0; ch < 16; ch++){
        if (ch == 15) asm volatile("cp.async.wait_group 0;" ::: "memory");
        else          asm volatile("cp.async.wait_group 1;" ::: "memory");
        __syncthreads();
        uint32_t ba = sb + (ch & 1) * G_STAGE;
#pragma unroll
        for (int k16 = 0; k16 < 4; k16++){
            uint32_t aoff = SW128((uint32_t)(ar*128 + (k16*2 + akh)*16));
            uint32_t ah[4], al[4];
            ldm4(ah, ba + aoff);
            ldm4(al, ba + 16384 + aoff);
#pragma unroll
            for (int np = 0; np < 8; np++){
                int bn  = np*16 + (grp >> 1)*8 + bi;
                int bkc = k16*2 + (grp & 1);
                uint32_t boff = SW128((uint32_t)(bn*128 + bkc*16));
                uint32_t w[4];
                ldm4(w, ba + 32768 + boff);
                mma_f16(acc[np*2],   ah, w[0], w[1]);
                mma_f16(acc[np*2+1], ah, w[2], w[3]);
                mma_f16(acc[np*2],   al, w[0], w[1]);
                mma_f16(acc[np*2+1], al, w[2], w[3]);
            }
        }
        __syncthreads();
        if (ch + 2 < 16) G_ISSUE(ch + 2, ch & 1);
    }
#undef G_ISSUE

    // epilogue
    const int r1 = m0 + R0 + (lane >> 2), r2 = r1 + 8;
#pragma unroll
    for (int nf = 0; nf < 16; nf++){
        int c = n0 + nf*8 + (lane & 3)*2;
        float v0 = acc[nf][0], v1 = acc[nf][1], v2 = acc[nf][2], v3 = acc[nf][3];
        if (bias){
            float2 bb = *(const float2*)(bias + c);
            v0 += bb.x; v1 += bb.y; v2 += bb.x; v3 += bb.y;
        }
        if (mode == 0){
            v0 *= 0.125f; v1 *= 0.125f; v2 *= 0.125f; v3 *= 0.125f;
            int h = c >> 6, dh = c & 63;
#pragma unroll
            for (int rr = 0; rr < 2; rr++){
                int row = rr ? r2 : r1;
                float a = rr ? v2 : v0, b2 = rr ? v3 : v1;
                int b = row >> 10, q = row & 1023;
                size_t o = (((size_t)b*HH + h)*TQ + q)*64 + dh;
                *(__half2*)(g_qhf + o) = __floats2half2_rn(a, b2);
            }
        } else if (mode == 3){
            *(float2*)(outp + (size_t)r1*DD + c) = make_float2(v0, v1);
            *(float2*)(outp + (size_t)r2*DD + c) = make_float2(v2, v3);
        } else {
            float* dst = (mode == 1) ? kout : vout;
            int h = c >> 6, dh = c & 63;
#pragma unroll
            for (int rr = 0; rr < 2; rr++){
                int row = rr ? r2 : r1;
                float a = rr ? v2 : v0, b2 = rr ? v3 : v1;
                int b = row >> 10, q = row & 1023;
                size_t o = ((size_t)b*TKV + TQ + q)*DD + c;
                *(float2*)(dst + o) = make_float2(a, b2);
                if (mode == 1){
                    size_t ko = (((size_t)b*HH + h)*TKV + TQ + q)*64 + dh;
                    *(__half2*)(g_khf + ko) = __floats2half2_rn(a, b2);
                }
            }
        }
    }
}

// ---------------- attention (fp16: 1-pass S, 2-pass PV) ----------------------
// smem: Q 16K | PH 32K | PL 32K | 3 stages x 32K {K fp16, V fp16}
#define A_QH 0
#define A_PH 16384
#define A_PL 49152
#define A_ST 81920
#define A_STAGE 32768
#define A_SMEM (81920 + 3*32768)     // 180224 (176KB)

__global__ void __launch_bounds__(256, 1) attn_tc(const float* __restrict__ mask){
    extern __shared__ char sm[];
    uint32_t sb = smem_u32(sm);
    const int tid = threadIdx.x, wid = tid >> 5, lane = tid & 31;
    const int q0 = blockIdx.x * 128, h = blockIdx.y, b = blockIdx.z;
    const size_t bh = (size_t)b * HH + h;
    const int R0 = wid * 16;

    const __half* Qf = g_qhf + (bh*TQ + q0)*64;
    const __half* Kf = g_khf + bh * (size_t)TKV * 64;
    const __half* Vf = g_vt  + bh * (size_t)64 * TKV;

    // Q (persistent, fp16)
#pragma unroll
    for (int i = 0; i < 4; i++){
        int f = i*256 + tid, r = f >> 3, kc = f & 7;
        cp16(sb + A_QH + SW128((uint32_t)(r*128 + kc*16)), Qf + f*8);
    }
    CP_COMMIT();

#define A_ISSUE(it) do { \
    int kv0_ = (it) * 128; \
    uint32_t base_ = sb + A_ST + ((it) % 3) * A_STAGE; \
    _Pragma("unroll") \
    for (int i_ = 0; i_ < 4; i_++){ \
        int f_ = i_*256 + tid; \
        int r_ = f_ >> 3, kc_ = f_ & 7; \
        cp16(base_ + SW128((uint32_t)(r_*128 + kc_*16)), Kf + (size_t)kv0_*64 + f_*8); \
        int r2_ = f_ >> 4, kc2_ = f_ & 15; \
        uint32_t d2_ = (uint32_t)(r2_*256 + ((kc2_ >> 3) << 7) + (((kc2_ & 7) ^ (r2_ & 7)) << 4)); \
        cp16(base_ + 16384 + d2_, Vf + (size_t)r2_*TKV + kv0_ + kc2_*8); \
    } \
    CP_COMMIT(); \
} while (0)

    A_ISSUE(0);
    A_ISSUE(1);

    float Oacc[8][4];
#pragma unroll
    for (int i = 0; i < 8; i++)
#pragma unroll
        for (int j = 0; j < 4; j++) Oacc[i][j] = 0.f;
    float rs0 = 0.f, rs1 = 0.f;

    const int r1l = R0 + (lane >> 2), r2l = r1l + 8;
    const int ar  = R0 + (lane & 15);
    const int akh = lane >> 4;
    const int bi  = lane & 7;
    const int grp = lane >> 3;
    const float* m1 = mask + (size_t)(q0 + r1l)*TKV + (lane & 3)*2;
    const float* m2 = m1 + 8*TKV;

    for (int it = 0; it < 16; it++){
        int kv0 = it * 128;
        if (it < 15) asm volatile("cp.async.wait_group 1;" ::: "memory");
        else         asm volatile("cp.async.wait_group 0;" ::: "memory");
        __syncthreads();
        uint32_t ba = sb + A_ST + (it % 3) * A_STAGE;

        // S = Q K^T (128x128), 1-pass fp16
        float Sacc[16][4];
#pragma unroll
        for (int i = 0; i < 16; i++)
#pragma unroll
            for (int j = 0; j < 4; j++) Sacc[i][j] = 0.f;
#pragma unroll
        for (int k16 = 0; k16 < 4; k16++){
            uint32_t aoff = SW128((uint32_t)(ar*128 + (k16*2 + akh)*16));
            uint32_t qh[4];
            ldm4(qh, sb + A_QH + aoff);
#pragma unroll
            for (int np = 0; np < 8; np++){
                int bn  = np*16 + (grp >> 1)*8 + bi;
                int bkc = k16*2 + (grp & 1);
                uint32_t boff = SW128((uint32_t)(bn*128 + bkc*16));
                uint32_t kh[4];
                ldm4(kh, ba + boff);
                mma_f16(Sacc[np*2],   qh, kh[0], kh[1]);
                mma_f16(Sacc[np*2+1], qh, kh[2], kh[3]);
            }
        }

        // P = exp(S + mask); row sums; store P fp16 hi/lo to smem
#pragma unroll
        for (int nf = 0; nf < 16; nf++){
            float2 ma = *(const float2*)(m1 + kv0 + nf*8);
            float2 mb = *(const float2*)(m2 + kv0 + nf*8);
            float p0 = __expf(Sacc[nf][0] + ma.x);
            float p1 = __expf(Sacc[nf][1] + ma.y);
            float p2 = __expf(Sacc[nf][2] + mb.x);
            float p3 = __expf(Sacc[nf][3] + mb.y);
            rs0 += p0 + p1; rs1 += p2 + p3;
            __half2 h01 = __floats2half2_rn(p0, p1);
            __half2 l01 = __floats2half2_rn(p0 - __low2float(h01), p1 - __high2float(h01));
            __half2 h23 = __floats2half2_rn(p2, p3);
            __half2 l23 = __floats2half2_rn(p2 - __low2float(h23), p3 - __high2float(h23));
            uint32_t o1 = (uint32_t)(r1l*256 + ((nf >> 3) << 7) + (((nf & 7) ^ (r1l & 7)) << 4) + (lane & 3)*4);
            uint32_t o2 = (uint32_t)(r2l*256 + ((nf >> 3) << 7) + (((nf & 7) ^ (r2l & 7)) << 4) + (lane & 3)*4);
            sts32(sb + A_PH + o1, h2u(h01));
            sts32(sb + A_PL + o1, h2u(l01));
            sts32(sb + A_PH + o2, h2u(h23));
            sts32(sb + A_PL + o2, h2u(l23));
        }
        __syncwarp();   // P rows are warp-private

        // O += P V^T (128x64 over k=128), 2-pass fp16 (split P, single V)
#pragma unroll
        for (int k16 = 0; k16 < 8; k16++){
            int pkc = k16*2 + akh;
            uint32_t poff = (uint32_t)(ar*256 + ((pkc >> 3) << 7) + (((pkc & 7) ^ (ar & 7)) << 4));
            uint32_t ph[4], pl[4];
            ldm4(ph, sb + A_PH + poff);
            ldm4(pl, sb + A_PL + poff);
#pragma unroll
            for (int np = 0; np < 4; np++){
                int vn  = np*16 + (grp >> 1)*8 + bi;
                int vkc = k16*2 + (grp & 1);
                uint32_t voff = (uint32_t)(vn*256 + ((vkc >> 3) << 7) + (((vkc & 7) ^ (vn & 7)) << 4));
                uint32_t vh[4];
                ldm4(vh, ba + 16384 + voff);
                mma_f16(Oacc[np*2],   ph, vh[0], vh[1]);
                mma_f16(Oacc[np*2+1], ph, vh[2], vh[3]);
                mma_f16(Oacc[np*2],   pl, vh[0], vh[1]);
                mma_f16(Oacc[np*2+1], pl, vh[2], vh[3]);
            }
        }

        // prefetch stage it+2 (buffer (it+2)%3 free: all warps passed this
        // iter's barrier, so iter it-1's reads of it are complete)
        if (it < 14) A_ISSUE(it + 2);
    }
#undef A_ISSUE

    // row-sum reduce across the 4 lanes sharing each row
    rs0 += __shfl_xor_sync(0xffffffffu, rs0, 1);
    rs0 += __shfl_xor_sync(0xffffffffu, rs0, 2);
    rs1 += __shfl_xor_sync(0xffffffffu, rs1, 1);
    rs1 += __shfl_xor_sync(0xffffffffu, rs1, 2);
    float inv0 = 1.f / rs0, inv1 = 1.f / rs1;

    // normalize + split fp16 + write attention output (head-major cols)
    size_t base1 = ((size_t)(b*TQ + q0 + r1l))*DD + h*64;
    size_t base2 = ((size_t)(b*TQ + q0 + r2l))*DD + h*64;
#pragma unroll
    for (int nf = 0; nf < 8; nf++){
        int c = nf*8 + (lane & 3)*2;
        float v0 = Oacc[nf][0]*inv0, v1 = Oacc[nf][1]*inv0;
        float v2 = Oacc[nf][2]*inv1, v3 = Oacc[nf][3]*inv1;
        __half ha, la, hb, lb;
        split2h(v0, ha, la); split2h(v1, hb, lb);
        *(__half2*)(g_avh + base1 + c) = __halves2half2(ha, hb);
        *(__half2*)(g_avl + base1 + c) = __halves2half2(la, lb);
        split2h(v2, ha, la); split2h(v3, hb, lb);
        *(__half2*)(g_avh + base2 + c) = __halves2half2(ha, hb);
        *(__half2*)(g_avl + base2 + c) = __halves2half2(la, lb);
    }
}

// ---------------- launch ----------------------------------------------------
extern "C" void kernel_launch(void* const* d_in, const int* in_sizes, int n_in,
                              void* d_out, int out_size) {
    const float* x       = (const float*)d_in[0];
    const float* k_cache = (const float*)d_in[1];
    const float* v_cache = (const float*)d_in[2];
    const float* mask    = (const float*)d_in[3];
    const float* Wq      = (const float*)d_in[4];
    const float* bq      = (const float*)d_in[5];
    const float* Wk      = (const float*)d_in[6];
    const float* Wv      = (const float*)d_in[7];
    const float* bv      = (const float*)d_in[8];
    const float* Wo      = (const float*)d_in[9];
    const float* bo      = (const float*)d_in[10];

    float* outp = (float*)d_out;
    float* kout = outp + (size_t)BB * TQ * DD;
    float* vout = kout + (size_t)BB * TKV * DD;

    static int attr_done = 0;
    if (!attr_done){
        cudaFuncSetAttribute(gemm_tc, cudaFuncAttributeMaxDynamicSharedMemorySize, G_SMEM);
        cudaFuncSetAttribute(attn_tc, cudaFuncAttributeMaxDynamicSharedMemorySize, A_SMEM);
        attr_done = 1;
    }

    // 1) old cache rows -> output (+ K fp16 operands for old rows)
    {
        int n4 = BB * TQ * DD / 4;
        copy_old_cache<<<(n4 + 255)/256, 256>>>(
            (const float4*)k_cache, (const float4*)v_cache,
            (float4*)kout, (float4*)vout);
    }
    // 2) conversions: x -> fp16 hi/lo, weights -> single fp16
    conv_x<<<(BB*TQ*DD/4 + 255)/256, 256>>>((const float4*)x, BB*TQ*DD/4);
    conv_w<<<(DD*DD/4 + 255)/256, 256>>>((const float4*)Wq, 0, DD*DD/4);
    conv_w<<<(DD*DD/4 + 255)/256, 256>>>((const float4*)Wk, 1, DD*DD/4);
    conv_w<<<(DD*DD/4 + 255)/256, 256>>>((const float4*)Wv, 2, DD*DD/4);
    conv_w<<<(DD*DD/4 + 255)/256, 256>>>((const float4*)Wo, 3, DD*DD/4);
    // 3) QKV projections (K fp16 operands fused in mode-1 epilogue)
    gemm_tc<<<dim3(DD/128, BB*TQ/128, 3), 256, G_SMEM>>>(0, bq, bv, bo, kout, vout, outp);
    // 4) V cache -> transposed fp16 operand
    vconv<<<dim3(TKV/128, HH, BB), 256>>>(vout);
    // 5) attention
    attn_tc<<<dim3(TQ/128, HH, BB), 256, A_SMEM>>>(mask);
    // 6) output projection
    gemm_tc<<<dim3(DD/128, BB*TQ/128, 1), 256, G_SMEM>>>(3, bq, bv, bo, kout, vout, outp);
}